// round 2
// baseline (speedup 1.0000x reference)
#include <cuda_runtime.h>

#define NPAPER 60000
#define NAUTH  30000
#define NEC    300000
#define NEW_   150000
#define NEB    150000
#define HIDDEN 512
#define NCLS   153

// ---------------- scratch (device globals; no allocation allowed) ----------------
__device__ float g_ZP0[(size_t)NPAPER * HIDDEN];
__device__ float g_ZP1[(size_t)NPAPER * HIDDEN];
__device__ float g_ZP2[(size_t)NPAPER * HIDDEN];
__device__ float g_ZA1[(size_t)NAUTH * HIDDEN];
__device__ float g_ZA2[(size_t)NAUTH * HIDDEN];
__device__ float g_OP [(size_t)NPAPER * HIDDEN];
__device__ float g_OA [(size_t)NAUTH * HIDDEN];
__device__ float g_elc[NPAPER * 4];
__device__ float g_erc[NPAPER * 4];
__device__ float g_elw[NAUTH  * 4];
__device__ float g_erw[NPAPER * 4];
__device__ float g_elb[NPAPER * 4];
__device__ float g_erb[NAUTH  * 4];
__device__ float g_jp [NPAPER * 4];
__device__ float g_ja [NAUTH  * 4];
__device__ float g_m  [NPAPER * 4];
__device__ float g_s  [NPAPER * 4];

// ---------------- utility kernels ----------------
__global__ void k_fill(float* __restrict__ p, float v, int n) {
    int i = blockIdx.x * blockDim.x + threadIdx.x;
    int stride = gridDim.x * blockDim.x;
    for (; i < n; i += stride) p[i] = v;
}

__global__ void k_relu(float* __restrict__ p, int n) {
    int i = blockIdx.x * blockDim.x + threadIdx.x;
    int stride = gridDim.x * blockDim.x;
    for (; i < n; i += stride) p[i] = fmaxf(p[i], 0.0f);
}

// ---------------- SGEMM: C[M,N] = A[M,K] @ B[K,N] (+bias) ----------------
// 128x128 block tile, BK=8, 256 threads, 8x8 per thread. Row-major A, B, C.
// NOTE: B loads use float4 only when N % 4 == 0 (alignment); scalar otherwise.
__global__ __launch_bounds__(256) void k_sgemm(
    const float* __restrict__ A, const float* __restrict__ B,
    float* __restrict__ C, int M, int N, int K,
    const float* __restrict__ bias)
{
    __shared__ float As[8][128];
    __shared__ float Bs[8][128];

    int tid = threadIdx.x;
    int bm = blockIdx.y * 128;
    int bn = blockIdx.x * 128;

    int aRow = tid >> 1;            // 0..127
    int aCol = (tid & 1) * 4;       // 0 or 4
    int bRow = tid >> 5;            // 0..7
    int bCol = (tid & 31) * 4;      // 0..124

    int tr = (tid >> 4) * 8;        // 0..120
    int tc = (tid & 15) * 8;        // 0..120

    float acc[8][8];
#pragma unroll
    for (int i = 0; i < 8; i++)
#pragma unroll
        for (int j = 0; j < 8; j++) acc[i][j] = 0.0f;

    bool aValid = (bm + aRow) < M;
    const float* Ap = A + (size_t)(bm + aRow) * K + aCol;
    bool nAligned = (N & 3) == 0;
    bool bFull = (bn + bCol + 3) < N;

    for (int k0 = 0; k0 < K; k0 += 8) {
        float4 a4 = make_float4(0.f, 0.f, 0.f, 0.f);
        if (aValid) a4 = *(const float4*)(Ap + k0);

        const float* bsrc = B + (size_t)(k0 + bRow) * N + bn + bCol;
        float4 b4;
        if (nAligned && bFull) {
            b4 = *(const float4*)bsrc;
        } else {
            b4.x = (bn + bCol + 0) < N ? bsrc[0] : 0.f;
            b4.y = (bn + bCol + 1) < N ? bsrc[1] : 0.f;
            b4.z = (bn + bCol + 2) < N ? bsrc[2] : 0.f;
            b4.w = (bn + bCol + 3) < N ? bsrc[3] : 0.f;
        }

        __syncthreads();
        As[aCol + 0][aRow] = a4.x;
        As[aCol + 1][aRow] = a4.y;
        As[aCol + 2][aRow] = a4.z;
        As[aCol + 3][aRow] = a4.w;
        *(float4*)&Bs[bRow][bCol] = b4;
        __syncthreads();

#pragma unroll
        for (int k = 0; k < 8; k++) {
            float ar_[8], br_[8];
#pragma unroll
            for (int i = 0; i < 8; i++) ar_[i] = As[k][tr + i];
#pragma unroll
            for (int j = 0; j < 8; j++) br_[j] = Bs[k][tc + j];
#pragma unroll
            for (int i = 0; i < 8; i++)
#pragma unroll
                for (int j = 0; j < 8; j++)
                    acc[i][j] = fmaf(ar_[i], br_[j], acc[i][j]);
        }
    }

#pragma unroll
    for (int i = 0; i < 8; i++) {
        int r = bm + tr + i;
        if (r >= M) continue;
#pragma unroll
        for (int j = 0; j < 8; j++) {
            int c = bn + tc + j;
            if (c < N) {
                float v = acc[i][j];
                if (bias) v += bias[c];
                C[(size_t)r * N + c] = v;
            }
        }
    }
}

// ---------------- attention logit dots: el[n,h]=sum_d Z[n,h,d]*al[h,d]; er likewise ----------------
// one warp per node; lane L handles float4 idx i*32+L (head = i)
__global__ void k_dots(const float* __restrict__ Z,
                       const float* __restrict__ al, const float* __restrict__ ar,
                       float* __restrict__ el, float* __restrict__ er, int Nn)
{
    int warp = (blockIdx.x * blockDim.x + threadIdx.x) >> 5;
    int lane = threadIdx.x & 31;
    if (warp >= Nn) return;
    const float4* zp = (const float4*)Z + (size_t)warp * 128;
    const float4* alp = (const float4*)al;
    const float4* arp = (const float4*)ar;
    float sl[4], sr[4];
#pragma unroll
    for (int i = 0; i < 4; i++) {
        float4 z = zp[i * 32 + lane];
        float4 a = alp[i * 32 + lane];
        float4 r = arp[i * 32 + lane];
        sl[i] = z.x * a.x + z.y * a.y + z.z * a.z + z.w * a.w;
        sr[i] = z.x * r.x + z.y * r.y + z.z * r.z + z.w * r.w;
    }
#pragma unroll
    for (int off = 16; off > 0; off >>= 1) {
#pragma unroll
        for (int i = 0; i < 4; i++) {
            sl[i] += __shfl_down_sync(0xffffffffu, sl[i], off);
            sr[i] += __shfl_down_sync(0xffffffffu, sr[i], off);
        }
    }
    if (lane == 0) {
#pragma unroll
        for (int i = 0; i < 4; i++) {
            el[warp * 4 + i] = sl[i];
            er[warp * 4 + i] = sr[i];
        }
    }
}

// ---------------- edge softmax passes ----------------
__device__ __forceinline__ float leaky02(float v) { return v > 0.f ? v : 0.2f * v; }

__device__ __forceinline__ void atomicMaxF(float* addr, float val) {
    int* ai = (int*)addr;
    int old = *ai;
    while (__int_as_float(old) < val) {
        int assumed = old;
        old = atomicCAS(ai, assumed, __float_as_int(val));
        if (old == assumed) break;
    }
}

__global__ void k_edge_max(const int* __restrict__ src, const int* __restrict__ dst,
                           const float* __restrict__ el, const float* __restrict__ er,
                           float* __restrict__ m, int E)
{
    int i = blockIdx.x * blockDim.x + threadIdx.x;
    if (i >= E * 4) return;
    int e = i >> 2, h = i & 3;
    int sn = src[e], dn = dst[e];
    float v = leaky02(el[sn * 4 + h] + er[dn * 4 + h]);
    atomicMaxF(&m[dn * 4 + h], v);
}

__global__ void k_edge_sum(const int* __restrict__ src, const int* __restrict__ dst,
                           const float* __restrict__ el, const float* __restrict__ er,
                           const float* __restrict__ m, float* __restrict__ s, int E)
{
    int i = blockIdx.x * blockDim.x + threadIdx.x;
    if (i >= E * 4) return;
    int e = i >> 2, h = i & 3;
    int sn = src[e], dn = dst[e];
    float v = leaky02(el[sn * 4 + h] + er[dn * 4 + h]);
    float ee = expf(v - m[dn * 4 + h]);
    atomicAdd(&s[dn * 4 + h], ee);
}

// one warp per edge: out[dst, h, :] += a[h] * Z[src, h, :], via red.global.add.v4
__global__ void k_edge_agg(const int* __restrict__ src, const int* __restrict__ dst,
                           const float* __restrict__ el, const float* __restrict__ er,
                           const float* __restrict__ m, const float* __restrict__ s,
                           const float* __restrict__ Z, float* __restrict__ out, int E)
{
    int gw = (blockIdx.x * blockDim.x + threadIdx.x) >> 5;
    if (gw >= E) return;
    int lane = threadIdx.x & 31;
    int sn = src[gw], dn = dst[gw];

    float4 e4 = ((const float4*)el)[sn];
    float4 r4 = ((const float4*)er)[dn];
    float4 m4 = ((const float4*)m)[dn];
    float4 s4 = ((const float4*)s)[dn];

    float a[4];
    a[0] = expf(leaky02(e4.x + r4.x) - m4.x) / (s4.x + 1e-9f);
    a[1] = expf(leaky02(e4.y + r4.y) - m4.y) / (s4.y + 1e-9f);
    a[2] = expf(leaky02(e4.z + r4.z) - m4.z) / (s4.z + 1e-9f);
    a[3] = expf(leaky02(e4.w + r4.w) - m4.w) / (s4.w + 1e-9f);

    const float4* zp = (const float4*)Z + (size_t)sn * 128;
    float4* op = (float4*)out + (size_t)dn * 128;

#pragma unroll
    for (int j = 0; j < 4; j++) {
        // float4 index j*32+lane -> element col (j*32+lane)*4 -> head = j
        float4 z = zp[j * 32 + lane];
        float aj = a[j];
        size_t gaddr = __cvta_generic_to_global(op + j * 32 + lane);
        asm volatile("red.global.add.v4.f32 [%0], {%1,%2,%3,%4};"
                     :: "l"(gaddr), "f"(aj * z.x), "f"(aj * z.y),
                        "f"(aj * z.z), "f"(aj * z.w)
                     : "memory");
    }
}

// ---------------- host-side launch helpers ----------------
static inline void launch_gemm(const float* A, const float* B, float* C,
                               int M, int N, int K, const float* bias)
{
    dim3 grid((N + 127) / 128, (M + 127) / 128);
    k_sgemm<<<grid, 256>>>(A, B, C, M, N, K, bias);
}

static inline void launch_fill(float* p, float v, int n)
{
    int blocks = (n + 255) / 256;
    if (blocks > 2048) blocks = 2048;
    k_fill<<<blocks, 256>>>(p, v, n);
}

static inline void launch_dots(const float* Z, const float* al, const float* ar,
                               float* el, float* er, int Nn)
{
    int threads = Nn * 32;
    k_dots<<<(threads + 255) / 256, 256>>>(Z, al, ar, el, er, Nn);
}

static inline void launch_edge_type(const int* src, const int* dst,
                                    const float* el, const float* er,
                                    float* m, float* s,
                                    const float* Z, float* out,
                                    int E, int nDst)
{
    launch_fill(m, -1e30f, nDst * 4);
    launch_fill(s, 0.0f, nDst * 4);
    int t4 = E * 4;
    k_edge_max<<<(t4 + 255) / 256, 256>>>(src, dst, el, er, m, E);
    k_edge_sum<<<(t4 + 255) / 256, 256>>>(src, dst, el, er, m, s, E);
    int t32 = E * 32;
    k_edge_agg<<<(t32 + 255) / 256, 256>>>(src, dst, el, er, m, s, Z, out, E);
}

extern "C" void kernel_launch(void* const* d_in, const int* in_sizes, int n_in,
                              void* d_out, int out_size)
{
    const float* x_paper  = (const float*)d_in[0];
    const float* x_author = (const float*)d_in[1];
    const int* cs = (const int*)d_in[2];
    const int* cd = (const int*)d_in[3];
    const int* ws = (const int*)d_in[4];
    const int* wd = (const int*)d_in[5];
    const int* bsrc = (const int*)d_in[6];
    const int* bdst = (const int*)d_in[7];
    const float* Wt[3] = { (const float*)d_in[8],  (const float*)d_in[11], (const float*)d_in[14] };
    const float* AL[3] = { (const float*)d_in[9],  (const float*)d_in[12], (const float*)d_in[15] };
    const float* AR[3] = { (const float*)d_in[10], (const float*)d_in[13], (const float*)d_in[16] };
    const float* linW = (const float*)d_in[17];
    const float* linb = (const float*)d_in[18];
    float* out = (float*)d_out;

    float *ZP0, *ZP1, *ZP2, *ZA1, *ZA2, *OP, *OA;
    float *elc, *erc, *elw, *erw, *elb, *erb, *jp, *ja, *mbuf, *sbuf;
    cudaGetSymbolAddress((void**)&ZP0, g_ZP0);
    cudaGetSymbolAddress((void**)&ZP1, g_ZP1);
    cudaGetSymbolAddress((void**)&ZP2, g_ZP2);
    cudaGetSymbolAddress((void**)&ZA1, g_ZA1);
    cudaGetSymbolAddress((void**)&ZA2, g_ZA2);
    cudaGetSymbolAddress((void**)&OP,  g_OP);
    cudaGetSymbolAddress((void**)&OA,  g_OA);
    cudaGetSymbolAddress((void**)&elc, g_elc);
    cudaGetSymbolAddress((void**)&erc, g_erc);
    cudaGetSymbolAddress((void**)&elw, g_elw);
    cudaGetSymbolAddress((void**)&erw, g_erw);
    cudaGetSymbolAddress((void**)&elb, g_elb);
    cudaGetSymbolAddress((void**)&erb, g_erb);
    cudaGetSymbolAddress((void**)&jp,  g_jp);
    cudaGetSymbolAddress((void**)&ja,  g_ja);
    cudaGetSymbolAddress((void**)&mbuf, g_m);
    cudaGetSymbolAddress((void**)&sbuf, g_s);

    for (int L = 0; L < 3; ++L) {
        const float* hp = (L == 0) ? x_paper  : OP;
        const float* ha = (L == 0) ? x_author : OA;
        int K = (L == 0) ? 1024 : 512;
        const float* W = Wt[L];
        const float* al = AL[L];
        const float* ar = AR[L];
        size_t wstride = (size_t)K * HIDDEN;

        // z = h @ W for every (node type, relation) pair needed
        launch_gemm(hp, W + 0 * wstride, ZP0, NPAPER, HIDDEN, K, nullptr);
        launch_gemm(hp, W + 1 * wstride, ZP1, NPAPER, HIDDEN, K, nullptr);
        launch_gemm(hp, W + 2 * wstride, ZP2, NPAPER, HIDDEN, K, nullptr);
        launch_gemm(ha, W + 1 * wstride, ZA1, NAUTH, HIDDEN, K, nullptr);
        launch_gemm(ha, W + 2 * wstride, ZA2, NAUTH, HIDDEN, K, nullptr);

        // attention logits
        launch_dots(ZP0, al + 0,    ar + 0,    elc, erc, NPAPER); // cites: src=paper, dst=paper
        launch_dots(ZA1, al + 512,  ar + 512,  elw, ja,  NAUTH);  // writes: src=author (el)
        launch_dots(ZP1, al + 512,  ar + 512,  jp,  erw, NPAPER); // writes: dst=paper (er)
        launch_dots(ZP2, al + 1024, ar + 1024, elb, jp,  NPAPER); // wb: src=paper (el)
        launch_dots(ZA2, al + 1024, ar + 1024, ja,  erb, NAUTH);  // wb: dst=author (er)

        // zero accumulators (after GEMMs have consumed OP/OA as inputs)
        launch_fill(OP, 0.0f, NPAPER * HIDDEN);
        launch_fill(OA, 0.0f, NAUTH * HIDDEN);

        // cites: paper -> paper
        launch_edge_type(cs, cd, elc, erc, mbuf, sbuf, ZP0, OP, NEC, NPAPER);
        // writes: author -> paper (accumulates into same OP: hetero sum-aggregate)
        launch_edge_type(ws, wd, elw, erw, mbuf, sbuf, ZA1, OP, NEW_, NPAPER);
        // written-by: paper -> author
        launch_edge_type(bsrc, bdst, elb, erb, mbuf, sbuf, ZP2, OA, NEB, NAUTH);

        if (L < 2) {
            int blocks = 2048;
            k_relu<<<blocks, 256>>>(OP, NPAPER * HIDDEN);
            k_relu<<<blocks, 256>>>(OA, NAUTH * HIDDEN);
        }
    }

    // classifier: out = hp_final @ linW + linb
    launch_gemm(OP, linW, out, NPAPER, NCLS, HIDDEN, linb);
}

// round 3
// speedup vs baseline: 2.3527x; 2.3527x over previous
#include <cuda_runtime.h>

#define NPAPER 60000
#define NAUTH  30000
#define NEC    300000
#define NEW_   150000
#define NEB    150000
#define HIDDEN 512
#define NCLS   153

// ---------------- scratch (device globals; no allocation allowed) ----------------
__device__ float g_ZP0[(size_t)NPAPER * HIDDEN];
__device__ float g_ZP1[(size_t)NPAPER * HIDDEN];
__device__ float g_ZP2[(size_t)NPAPER * HIDDEN];
__device__ float g_ZA1[(size_t)NAUTH * HIDDEN];
__device__ float g_ZA2[(size_t)NAUTH * HIDDEN];
__device__ float g_OP [(size_t)NPAPER * HIDDEN];
__device__ float g_OA [(size_t)NAUTH * HIDDEN];
__device__ float g_elc[NPAPER * 4];
__device__ float g_erc[NPAPER * 4];
__device__ float g_elw[NAUTH  * 4];
__device__ float g_erw[NPAPER * 4];
__device__ float g_elb[NPAPER * 4];
__device__ float g_erb[NAUTH  * 4];
__device__ float g_jp [NPAPER * 4];
__device__ float g_ja [NAUTH  * 4];
__device__ float g_m  [NPAPER * 4];
__device__ float g_s  [NPAPER * 4];

// ---------------- utility kernels ----------------
__global__ void k_fill(float* __restrict__ p, float v, int n) {
    int i = blockIdx.x * blockDim.x + threadIdx.x;
    int stride = gridDim.x * blockDim.x;
    for (; i < n; i += stride) p[i] = v;
}

__global__ void k_relu(float* __restrict__ p, int n) {
    int i = blockIdx.x * blockDim.x + threadIdx.x;
    int stride = gridDim.x * blockDim.x;
    for (; i < n; i += stride) p[i] = fmaxf(p[i], 0.0f);
}

// ---------------- TF32 tensor-core GEMM ----------------
// C[M,N] = A[M,K] @ B[K,N], row-major. Requires N % 128 == 0, K % 16 == 0.
// 128x128 block tile, BK=16, 256 threads = 8 warps in 4(m) x 2(n),
// warp tile 32x64 = 2x8 m16n8k8 mma tiles. Double-buffered SMEM, pad=8.

__device__ __forceinline__ unsigned f2tf32(float f) {
    unsigned u;
    asm("cvt.rna.tf32.f32 %0, %1;" : "=r"(u) : "f"(f));
    return u;
}

#define TBM 128
#define TBN 128
#define TBK 16
#define TPAD 8

__global__ __launch_bounds__(256) void k_tf32_gemm(
    const float* __restrict__ A, const float* __restrict__ B,
    float* __restrict__ C, int M, int N, int K)
{
    __shared__ float As[2][TBK][TBM + TPAD];
    __shared__ float Bs[2][TBK][TBN + TPAD];

    int tid = threadIdx.x;
    int lane = tid & 31;
    int wid = tid >> 5;
    int warp_m = wid & 3;   // 0..3 -> 32 rows each
    int warp_n = wid >> 2;  // 0..1 -> 64 cols each
    int gr = lane >> 2;     // 0..7
    int gc = lane & 3;      // 0..3

    int bm = blockIdx.y * TBM;
    int bn = blockIdx.x * TBN;

    // global load indexing
    // A tile: 128 rows x 4 float4 -> f4 idx i = tid + p*256 : row=i>>2, c4=i&3
    // B tile: 16 rows x 32 float4 -> f4 idx i = tid + p*256 : row=i>>5, c4=i&31
    int aRow0 = tid >> 2;          // + p*64
    int aC4   = tid & 3;
    int bRow0 = tid >> 5;          // + p*8
    int bC4   = tid & 31;

    float acc[2][8][4];
#pragma unroll
    for (int mi = 0; mi < 2; mi++)
#pragma unroll
        for (int ni = 0; ni < 8; ni++)
#pragma unroll
            for (int j = 0; j < 4; j++) acc[mi][ni][j] = 0.0f;

    int ntiles = K / TBK;

    float4 aReg[2], bReg[2];

    // ---- prologue: load tile 0 into regs, store to buffer 0 ----
#pragma unroll
    for (int p = 0; p < 2; p++) {
        int ar = aRow0 + p * 64;
        aReg[p] = make_float4(0.f, 0.f, 0.f, 0.f);
        if (bm + ar < M)
            aReg[p] = *(const float4*)(A + (size_t)(bm + ar) * K + aC4 * 4);
        int br = bRow0 + p * 8;
        bReg[p] = *(const float4*)(B + (size_t)br * N + bn + bC4 * 4);
    }
#pragma unroll
    for (int p = 0; p < 2; p++) {
        int ar = aRow0 + p * 64;
        As[0][aC4 * 4 + 0][ar] = __uint_as_float(f2tf32(aReg[p].x));
        As[0][aC4 * 4 + 1][ar] = __uint_as_float(f2tf32(aReg[p].y));
        As[0][aC4 * 4 + 2][ar] = __uint_as_float(f2tf32(aReg[p].z));
        As[0][aC4 * 4 + 3][ar] = __uint_as_float(f2tf32(aReg[p].w));
        int br = bRow0 + p * 8;
        float* bp = &Bs[0][br][bC4 * 4];
        bp[0] = __uint_as_float(f2tf32(bReg[p].x));
        bp[1] = __uint_as_float(f2tf32(bReg[p].y));
        bp[2] = __uint_as_float(f2tf32(bReg[p].z));
        bp[3] = __uint_as_float(f2tf32(bReg[p].w));
    }
    __syncthreads();

#pragma unroll 1
    for (int t = 0; t < ntiles; t++) {
        int buf = t & 1;

        // prefetch next tile into registers
        if (t + 1 < ntiles) {
            int k0 = (t + 1) * TBK;
#pragma unroll
            for (int p = 0; p < 2; p++) {
                int ar = aRow0 + p * 64;
                aReg[p] = make_float4(0.f, 0.f, 0.f, 0.f);
                if (bm + ar < M)
                    aReg[p] = *(const float4*)(A + (size_t)(bm + ar) * K + k0 + aC4 * 4);
                int br = bRow0 + p * 8;
                bReg[p] = *(const float4*)(B + (size_t)(k0 + br) * N + bn + bC4 * 4);
            }
        }

        // compute on current buffer
#pragma unroll
        for (int ks = 0; ks < 2; ks++) {
            int k0 = ks * 8;
            unsigned af[2][4];
#pragma unroll
            for (int mi = 0; mi < 2; mi++) {
                int m0 = warp_m * 32 + mi * 16 + gr;
                af[mi][0] = __float_as_uint(As[buf][k0 + gc][m0]);
                af[mi][1] = __float_as_uint(As[buf][k0 + gc][m0 + 8]);
                af[mi][2] = __float_as_uint(As[buf][k0 + gc + 4][m0]);
                af[mi][3] = __float_as_uint(As[buf][k0 + gc + 4][m0 + 8]);
            }
            unsigned bf[8][2];
#pragma unroll
            for (int ni = 0; ni < 8; ni++) {
                int n0 = warp_n * 64 + ni * 8 + gr;
                bf[ni][0] = __float_as_uint(Bs[buf][k0 + gc][n0]);
                bf[ni][1] = __float_as_uint(Bs[buf][k0 + gc + 4][n0]);
            }
#pragma unroll
            for (int mi = 0; mi < 2; mi++)
#pragma unroll
                for (int ni = 0; ni < 8; ni++) {
                    asm volatile(
                        "mma.sync.aligned.m16n8k8.row.col.f32.tf32.tf32.f32 "
                        "{%0,%1,%2,%3}, {%4,%5,%6,%7}, {%8,%9}, {%0,%1,%2,%3};"
                        : "+f"(acc[mi][ni][0]), "+f"(acc[mi][ni][1]),
                          "+f"(acc[mi][ni][2]), "+f"(acc[mi][ni][3])
                        : "r"(af[mi][0]), "r"(af[mi][1]), "r"(af[mi][2]), "r"(af[mi][3]),
                          "r"(bf[ni][0]), "r"(bf[ni][1]));
                }
        }

        // store prefetched tile into other buffer
        if (t + 1 < ntiles) {
            int nbuf = 1 - buf;
#pragma unroll
            for (int p = 0; p < 2; p++) {
                int ar = aRow0 + p * 64;
                As[nbuf][aC4 * 4 + 0][ar] = __uint_as_float(f2tf32(aReg[p].x));
                As[nbuf][aC4 * 4 + 1][ar] = __uint_as_float(f2tf32(aReg[p].y));
                As[nbuf][aC4 * 4 + 2][ar] = __uint_as_float(f2tf32(aReg[p].z));
                As[nbuf][aC4 * 4 + 3][ar] = __uint_as_float(f2tf32(aReg[p].w));
                int br = bRow0 + p * 8;
                float* bp = &Bs[nbuf][br][bC4 * 4];
                bp[0] = __uint_as_float(f2tf32(bReg[p].x));
                bp[1] = __uint_as_float(f2tf32(bReg[p].y));
                bp[2] = __uint_as_float(f2tf32(bReg[p].z));
                bp[3] = __uint_as_float(f2tf32(bReg[p].w));
            }
        }
        __syncthreads();
    }

    // ---- epilogue: write C ----
#pragma unroll
    for (int mi = 0; mi < 2; mi++) {
#pragma unroll
        for (int ni = 0; ni < 8; ni++) {
            int r0 = bm + warp_m * 32 + mi * 16 + gr;
            int cn = bn + warp_n * 64 + ni * 8 + gc * 2;
            if (r0 < M) {
                float2 v = make_float2(acc[mi][ni][0], acc[mi][ni][1]);
                *(float2*)(C + (size_t)r0 * N + cn) = v;
            }
            if (r0 + 8 < M) {
                float2 v = make_float2(acc[mi][ni][2], acc[mi][ni][3]);
                *(float2*)(C + (size_t)(r0 + 8) * N + cn) = v;
            }
        }
    }
}

// ---------------- SIMT SGEMM (classifier only, N=153) ----------------
__global__ __launch_bounds__(256) void k_sgemm(
    const float* __restrict__ A, const float* __restrict__ B,
    float* __restrict__ C, int M, int N, int K,
    const float* __restrict__ bias)
{
    __shared__ float As[8][128];
    __shared__ float Bs[8][128];

    int tid = threadIdx.x;
    int bm = blockIdx.y * 128;
    int bn = blockIdx.x * 128;

    int aRow = tid >> 1;
    int aCol = (tid & 1) * 4;
    int bRow = tid >> 5;
    int bCol = (tid & 31) * 4;

    int tr = (tid >> 4) * 8;
    int tc = (tid & 15) * 8;

    float acc[8][8];
#pragma unroll
    for (int i = 0; i < 8; i++)
#pragma unroll
        for (int j = 0; j < 8; j++) acc[i][j] = 0.0f;

    bool aValid = (bm + aRow) < M;
    const float* Ap = A + (size_t)(bm + aRow) * K + aCol;
    bool nAligned = (N & 3) == 0;
    bool bFull = (bn + bCol + 3) < N;

    for (int k0 = 0; k0 < K; k0 += 8) {
        float4 a4 = make_float4(0.f, 0.f, 0.f, 0.f);
        if (aValid) a4 = *(const float4*)(Ap + k0);

        const float* bsrc = B + (size_t)(k0 + bRow) * N + bn + bCol;
        float4 b4;
        if (nAligned && bFull) {
            b4 = *(const float4*)bsrc;
        } else {
            b4.x = (bn + bCol + 0) < N ? bsrc[0] : 0.f;
            b4.y = (bn + bCol + 1) < N ? bsrc[1] : 0.f;
            b4.z = (bn + bCol + 2) < N ? bsrc[2] : 0.f;
            b4.w = (bn + bCol + 3) < N ? bsrc[3] : 0.f;
        }

        __syncthreads();
        As[aCol + 0][aRow] = a4.x;
        As[aCol + 1][aRow] = a4.y;
        As[aCol + 2][aRow] = a4.z;
        As[aCol + 3][aRow] = a4.w;
        *(float4*)&Bs[bRow][bCol] = b4;
        __syncthreads();

#pragma unroll
        for (int k = 0; k < 8; k++) {
            float ar_[8], br_[8];
#pragma unroll
            for (int i = 0; i < 8; i++) ar_[i] = As[k][tr + i];
#pragma unroll
            for (int j = 0; j < 8; j++) br_[j] = Bs[k][tc + j];
#pragma unroll
            for (int i = 0; i < 8; i++)
#pragma unroll
                for (int j = 0; j < 8; j++)
                    acc[i][j] = fmaf(ar_[i], br_[j], acc[i][j]);
        }
    }

#pragma unroll
    for (int i = 0; i < 8; i++) {
        int r = bm + tr + i;
        if (r >= M) continue;
#pragma unroll
        for (int j = 0; j < 8; j++) {
            int c = bn + tc + j;
            if (c < N) {
                float v = acc[i][j];
                if (bias) v += bias[c];
                C[(size_t)r * N + c] = v;
            }
        }
    }
}

// ---------------- attention logit dots ----------------
__global__ void k_dots(const float* __restrict__ Z,
                       const float* __restrict__ al, const float* __restrict__ ar,
                       float* __restrict__ el, float* __restrict__ er, int Nn)
{
    int warp = (blockIdx.x * blockDim.x + threadIdx.x) >> 5;
    int lane = threadIdx.x & 31;
    if (warp >= Nn) return;
    const float4* zp = (const float4*)Z + (size_t)warp * 128;
    const float4* alp = (const float4*)al;
    const float4* arp = (const float4*)ar;
    float sl[4], sr[4];
#pragma unroll
    for (int i = 0; i < 4; i++) {
        float4 z = zp[i * 32 + lane];
        float4 a = alp[i * 32 + lane];
        float4 r = arp[i * 32 + lane];
        sl[i] = z.x * a.x + z.y * a.y + z.z * a.z + z.w * a.w;
        sr[i] = z.x * r.x + z.y * r.y + z.z * r.z + z.w * r.w;
    }
#pragma unroll
    for (int off = 16; off > 0; off >>= 1) {
#pragma unroll
        for (int i = 0; i < 4; i++) {
            sl[i] += __shfl_down_sync(0xffffffffu, sl[i], off);
            sr[i] += __shfl_down_sync(0xffffffffu, sr[i], off);
        }
    }
    if (lane == 0) {
#pragma unroll
        for (int i = 0; i < 4; i++) {
            el[warp * 4 + i] = sl[i];
            er[warp * 4 + i] = sr[i];
        }
    }
}

// ---------------- edge softmax passes ----------------
__device__ __forceinline__ float leaky02(float v) { return v > 0.f ? v : 0.2f * v; }

__device__ __forceinline__ void atomicMaxF(float* addr, float val) {
    int* ai = (int*)addr;
    int old = *ai;
    while (__int_as_float(old) < val) {
        int assumed = old;
        old = atomicCAS(ai, assumed, __float_as_int(val));
        if (old == assumed) break;
    }
}

__global__ void k_edge_max(const int* __restrict__ src, const int* __restrict__ dst,
                           const float* __restrict__ el, const float* __restrict__ er,
                           float* __restrict__ m, int E)
{
    int i = blockIdx.x * blockDim.x + threadIdx.x;
    if (i >= E * 4) return;
    int e = i >> 2, h = i & 3;
    int sn = src[e], dn = dst[e];
    float v = leaky02(el[sn * 4 + h] + er[dn * 4 + h]);
    atomicMaxF(&m[dn * 4 + h], v);
}

__global__ void k_edge_sum(const int* __restrict__ src, const int* __restrict__ dst,
                           const float* __restrict__ el, const float* __restrict__ er,
                           const float* __restrict__ m, float* __restrict__ s, int E)
{
    int i = blockIdx.x * blockDim.x + threadIdx.x;
    if (i >= E * 4) return;
    int e = i >> 2, h = i & 3;
    int sn = src[e], dn = dst[e];
    float v = leaky02(el[sn * 4 + h] + er[dn * 4 + h]);
    float ee = expf(v - m[dn * 4 + h]);
    atomicAdd(&s[dn * 4 + h], ee);
}

__global__ void k_edge_agg(const int* __restrict__ src, const int* __restrict__ dst,
                           const float* __restrict__ el, const float* __restrict__ er,
                           const float* __restrict__ m, const float* __restrict__ s,
                           const float* __restrict__ Z, float* __restrict__ out, int E)
{
    int gw = (blockIdx.x * blockDim.x + threadIdx.x) >> 5;
    if (gw >= E) return;
    int lane = threadIdx.x & 31;
    int sn = src[gw], dn = dst[gw];

    float4 e4 = ((const float4*)el)[sn];
    float4 r4 = ((const float4*)er)[dn];
    float4 m4 = ((const float4*)m)[dn];
    float4 s4 = ((const float4*)s)[dn];

    float a[4];
    a[0] = expf(leaky02(e4.x + r4.x) - m4.x) / (s4.x + 1e-9f);
    a[1] = expf(leaky02(e4.y + r4.y) - m4.y) / (s4.y + 1e-9f);
    a[2] = expf(leaky02(e4.z + r4.z) - m4.z) / (s4.z + 1e-9f);
    a[3] = expf(leaky02(e4.w + r4.w) - m4.w) / (s4.w + 1e-9f);

    const float4* zp = (const float4*)Z + (size_t)sn * 128;
    float4* op = (float4*)out + (size_t)dn * 128;

#pragma unroll
    for (int j = 0; j < 4; j++) {
        float4 z = zp[j * 32 + lane];
        float aj = a[j];
        size_t gaddr = __cvta_generic_to_global(op + j * 32 + lane);
        asm volatile("red.global.add.v4.f32 [%0], {%1,%2,%3,%4};"
                     :: "l"(gaddr), "f"(aj * z.x), "f"(aj * z.y),
                        "f"(aj * z.z), "f"(aj * z.w)
                     : "memory");
    }
}

// ---------------- host-side launch helpers ----------------
static inline void launch_gemm_tc(const float* A, const float* B, float* C,
                                  int M, int N, int K)
{
    dim3 grid(N / 128, (M + 127) / 128);
    k_tf32_gemm<<<grid, 256>>>(A, B, C, M, N, K);
}

static inline void launch_gemm_simt(const float* A, const float* B, float* C,
                                    int M, int N, int K, const float* bias)
{
    dim3 grid((N + 127) / 128, (M + 127) / 128);
    k_sgemm<<<grid, 256>>>(A, B, C, M, N, K, bias);
}

static inline void launch_fill(float* p, float v, int n)
{
    int blocks = (n + 255) / 256;
    if (blocks > 2048) blocks = 2048;
    k_fill<<<blocks, 256>>>(p, v, n);
}

static inline void launch_dots(const float* Z, const float* al, const float* ar,
                               float* el, float* er, int Nn)
{
    int threads = Nn * 32;
    k_dots<<<(threads + 255) / 256, 256>>>(Z, al, ar, el, er, Nn);
}

static inline void launch_edge_type(const int* src, const int* dst,
                                    const float* el, const float* er,
                                    float* m, float* s,
                                    const float* Z, float* out,
                                    int E, int nDst)
{
    launch_fill(m, -1e30f, nDst * 4);
    launch_fill(s, 0.0f, nDst * 4);
    int t4 = E * 4;
    k_edge_max<<<(t4 + 255) / 256, 256>>>(src, dst, el, er, m, E);
    k_edge_sum<<<(t4 + 255) / 256, 256>>>(src, dst, el, er, m, s, E);
    int t32 = E * 32;
    k_edge_agg<<<(t32 + 255) / 256, 256>>>(src, dst, el, er, m, s, Z, out, E);
}

extern "C" void kernel_launch(void* const* d_in, const int* in_sizes, int n_in,
                              void* d_out, int out_size)
{
    const float* x_paper  = (const float*)d_in[0];
    const float* x_author = (const float*)d_in[1];
    const int* cs = (const int*)d_in[2];
    const int* cd = (const int*)d_in[3];
    const int* ws = (const int*)d_in[4];
    const int* wd = (const int*)d_in[5];
    const int* bsrc = (const int*)d_in[6];
    const int* bdst = (const int*)d_in[7];
    const float* Wt[3] = { (const float*)d_in[8],  (const float*)d_in[11], (const float*)d_in[14] };
    const float* AL[3] = { (const float*)d_in[9],  (const float*)d_in[12], (const float*)d_in[15] };
    const float* AR[3] = { (const float*)d_in[10], (const float*)d_in[13], (const float*)d_in[16] };
    const float* linW = (const float*)d_in[17];
    const float* linb = (const float*)d_in[18];
    float* out = (float*)d_out;

    float *ZP0, *ZP1, *ZP2, *ZA1, *ZA2, *OP, *OA;
    float *elc, *erc, *elw, *erw, *elb, *erb, *jp, *ja, *mbuf, *sbuf;
    cudaGetSymbolAddress((void**)&ZP0, g_ZP0);
    cudaGetSymbolAddress((void**)&ZP1, g_ZP1);
    cudaGetSymbolAddress((void**)&ZP2, g_ZP2);
    cudaGetSymbolAddress((void**)&ZA1, g_ZA1);
    cudaGetSymbolAddress((void**)&ZA2, g_ZA2);
    cudaGetSymbolAddress((void**)&OP,  g_OP);
    cudaGetSymbolAddress((void**)&OA,  g_OA);
    cudaGetSymbolAddress((void**)&elc, g_elc);
    cudaGetSymbolAddress((void**)&erc, g_erc);
    cudaGetSymbolAddress((void**)&elw, g_elw);
    cudaGetSymbolAddress((void**)&erw, g_erw);
    cudaGetSymbolAddress((void**)&elb, g_elb);
    cudaGetSymbolAddress((void**)&erb, g_erb);
    cudaGetSymbolAddress((void**)&jp,  g_jp);
    cudaGetSymbolAddress((void**)&ja,  g_ja);
    cudaGetSymbolAddress((void**)&mbuf, g_m);
    cudaGetSymbolAddress((void**)&sbuf, g_s);

    for (int L = 0; L < 3; ++L) {
        const float* hp = (L == 0) ? x_paper  : OP;
        const float* ha = (L == 0) ? x_author : OA;
        int K = (L == 0) ? 1024 : 512;
        const float* W = Wt[L];
        const float* al = AL[L];
        const float* ar = AR[L];
        size_t wstride = (size_t)K * HIDDEN;

        // z = h @ W for every (node type, relation) pair needed
        launch_gemm_tc(hp, W + 0 * wstride, ZP0, NPAPER, HIDDEN, K);
        launch_gemm_tc(hp, W + 1 * wstride, ZP1, NPAPER, HIDDEN, K);
        launch_gemm_tc(hp, W + 2 * wstride, ZP2, NPAPER, HIDDEN, K);
        launch_gemm_tc(ha, W + 1 * wstride, ZA1, NAUTH, HIDDEN, K);
        launch_gemm_tc(ha, W + 2 * wstride, ZA2, NAUTH, HIDDEN, K);

        // attention logits
        launch_dots(ZP0, al + 0,    ar + 0,    elc, erc, NPAPER);
        launch_dots(ZA1, al + 512,  ar + 512,  elw, ja,  NAUTH);
        launch_dots(ZP1, al + 512,  ar + 512,  jp,  erw, NPAPER);
        launch_dots(ZP2, al + 1024, ar + 1024, elb, jp,  NPAPER);
        launch_dots(ZA2, al + 1024, ar + 1024, ja,  erb, NAUTH);

        // zero accumulators (after GEMMs consumed OP/OA)
        launch_fill(OP, 0.0f, NPAPER * HIDDEN);
        launch_fill(OA, 0.0f, NAUTH * HIDDEN);

        // cites: paper -> paper
        launch_edge_type(cs, cd, elc, erc, mbuf, sbuf, ZP0, OP, NEC, NPAPER);
        // writes: author -> paper
        launch_edge_type(ws, wd, elw, erw, mbuf, sbuf, ZA1, OP, NEW_, NPAPER);
        // written-by: paper -> author
        launch_edge_type(bsrc, bdst, elb, erb, mbuf, sbuf, ZP2, OA, NEB, NAUTH);

        if (L < 2) {
            int blocks = 2048;
            k_relu<<<blocks, 256>>>(OP, NPAPER * HIDDEN);
            k_relu<<<blocks, 256>>>(OA, NAUTH * HIDDEN);
        }
    }

    // classifier: out = hp_final @ linW + linb
    launch_gemm_simt(OP, linW, out, NPAPER, NCLS, HIDDEN, linb);
}

// round 6
// speedup vs baseline: 2.7537x; 1.1704x over previous
#include <cuda_runtime.h>
#include <cstdint>

#define NPAPER 60000
#define NAUTH  30000
#define NEC    300000
#define NEW_   150000
#define NEB    150000
#define HIDDEN 512
#define NCLS   153

// ---------------- scratch (device globals; no allocation allowed) ----------------
__device__ float g_ZP0[(size_t)NPAPER * HIDDEN];
__device__ float g_ZP1[(size_t)NPAPER * HIDDEN];
__device__ float g_ZP2[(size_t)NPAPER * HIDDEN];
__device__ float g_ZA1[(size_t)NAUTH * HIDDEN];
__device__ float g_ZA2[(size_t)NAUTH * HIDDEN];
__device__ float g_OP [(size_t)NPAPER * HIDDEN];
__device__ float g_OA [(size_t)NAUTH * HIDDEN];
__device__ float g_Ap [(size_t)NPAPER * 1024];   // tf32-preconverted paper features
__device__ float g_Aa [(size_t)NAUTH  * 1024];   // tf32-preconverted author features
__device__ float g_Wc [(size_t)3 * 1024 * 512];  // tf32-preconverted layer weights
__device__ float g_elc[NPAPER * 4];
__device__ float g_erc[NPAPER * 4];
__device__ float g_elw[NAUTH  * 4];
__device__ float g_erw[NPAPER * 4];
__device__ float g_elb[NPAPER * 4];
__device__ float g_erb[NAUTH  * 4];
__device__ float g_jp [NPAPER * 4];
__device__ float g_ja [NAUTH  * 4];
// CSR scratch
__device__ int g_cnt [NPAPER];
__device__ int g_offc[NPAPER + 1];
__device__ int g_offw[NPAPER + 1];
__device__ int g_offb[NAUTH + 1];
__device__ int g_eidc[NEC];
__device__ int g_eidw[NEW_];
__device__ int g_eidb[NEB];

// ---------------- utility kernels ----------------
__global__ void k_izero(int* __restrict__ p, int n) {
    int i = blockIdx.x * blockDim.x + threadIdx.x;
    int stride = gridDim.x * blockDim.x;
    for (; i < n; i += stride) p[i] = 0;
}

// tf32 round-to-nearest pre-conversion, n4 = count/4
__global__ void k_cvt_tf32(const float* __restrict__ in, float* __restrict__ out, int n4) {
    int i = blockIdx.x * blockDim.x + threadIdx.x;
    int stride = gridDim.x * blockDim.x;
    for (; i < n4; i += stride) {
        float4 v = ((const float4*)in)[i];
        uint4 o;
        asm("cvt.rna.tf32.f32 %0, %1;" : "=r"(o.x) : "f"(v.x));
        asm("cvt.rna.tf32.f32 %0, %1;" : "=r"(o.y) : "f"(v.y));
        asm("cvt.rna.tf32.f32 %0, %1;" : "=r"(o.z) : "f"(v.z));
        asm("cvt.rna.tf32.f32 %0, %1;" : "=r"(o.w) : "f"(v.w));
        ((uint4*)out)[i] = o;
    }
}

// ---------------- CSR build: histogram / scan / scatter ----------------
__global__ void k_hist(const int* __restrict__ dst, int E, int* __restrict__ cnt) {
    int e = blockIdx.x * blockDim.x + threadIdx.x;
    if (e < E) atomicAdd(&cnt[dst[e]], 1);
}

// single-block exclusive scan (n <= ~60001), 1024 threads
__global__ void k_scan(const int* __restrict__ cnt, int* __restrict__ off, int n) {
    __shared__ int sh[1024];
    int tid = threadIdx.x;
    int C = (n + 1023) / 1024;
    int b = tid * C;
    int sum = 0;
    for (int i = 0; i < C; i++)
        if (b + i < n) sum += cnt[b + i];
    sh[tid] = sum;
    __syncthreads();
    for (int d = 1; d < 1024; d <<= 1) {
        int t = 0;
        if (tid >= d) t = sh[tid - d];
        __syncthreads();
        if (tid >= d) sh[tid] += t;
        __syncthreads();
    }
    int run = sh[tid] - sum;  // exclusive prefix for this thread's chunk
    for (int i = 0; i < C; i++) {
        if (b + i < n) { off[b + i] = run; run += cnt[b + i]; }
    }
    if (tid == 1023) off[n] = sh[1023];
}

__global__ void k_scatter(const int* __restrict__ dst, int E,
                          const int* __restrict__ off, int* __restrict__ cur,
                          int* __restrict__ eid) {
    int e = blockIdx.x * blockDim.x + threadIdx.x;
    if (e >= E) return;
    int d = dst[e];
    int p = off[d] + atomicAdd(&cur[d], 1);
    eid[p] = e;
}

// ---------------- TF32 tensor-core GEMM (mma.sync), cp.async loads ----------------
// C[M,N] = A[M,K] @ B[K,N], row-major, N % 128 == 0, K % 16 == 0.
// A, B already tf32-rounded. 128x128 tile, BK=16, 8 warps (4m x 2n), warp tile 32x64.
#define AS_STRIDE 20
#define BS_STRIDE 136

__device__ __forceinline__ uint32_t smem_u32(const void* p) {
    uint32_t a;
    asm("{ .reg .u64 t; cvta.to.shared.u64 t, %1; cvt.u32.u64 %0, t; }" : "=r"(a) : "l"(p));
    return a;
}

__device__ __forceinline__ void cp16(uint32_t s, const float* g, bool v) {
    asm volatile("cp.async.cg.shared.global [%0], [%1], 16, %2;"
                 :: "r"(s), "l"(__cvta_generic_to_global(g)), "r"(v ? 16 : 0));
}

__device__ __forceinline__ void gemm_issue_tile(
    float (*As)[128][AS_STRIDE], float (*Bs)[16][BS_STRIDE],
    int buf, const float* __restrict__ A, const float* __restrict__ B,
    int bm, int bn, int M, int N, int K, int k0, int tid)
{
    int am = tid >> 2, ac4 = tid & 3;
    int bk = tid >> 5, bc4 = tid & 31;
#pragma unroll
    for (int i = 0; i < 2; i++) {
        int m = am + i * 64;
        int mm = bm + m;
        int msafe = mm < M ? mm : (M - 1);
        cp16(smem_u32(&As[buf][m][ac4 * 4]),
             A + (size_t)msafe * K + k0 + ac4 * 4, mm < M);
    }
#pragma unroll
    for (int i = 0; i < 2; i++) {
        int kr = bk + i * 8;
        cp16(smem_u32(&Bs[buf][kr][bc4 * 4]),
             B + (size_t)(k0 + kr) * N + bn + bc4 * 4, true);
    }
    asm volatile("cp.async.commit_group;" ::: "memory");
}

__global__ __launch_bounds__(256) void k_tf32_gemm(
    const float* __restrict__ A, const float* __restrict__ B,
    float* __restrict__ C, int M, int N, int K)
{
    __shared__ float As[2][128][AS_STRIDE];
    __shared__ float Bs[2][16][BS_STRIDE];

    int tid = threadIdx.x;
    int lane = tid & 31;
    int wid = tid >> 5;
    int warp_m = wid & 3;
    int warp_n = wid >> 2;
    int gr = lane >> 2;
    int gc = lane & 3;

    int bm = blockIdx.y * 128;
    int bn = blockIdx.x * 128;

    float acc[2][8][4];
#pragma unroll
    for (int mi = 0; mi < 2; mi++)
#pragma unroll
        for (int ni = 0; ni < 8; ni++)
#pragma unroll
            for (int j = 0; j < 4; j++) acc[mi][ni][j] = 0.0f;

    int nt = K >> 4;

    gemm_issue_tile(As, Bs, 0, A, B, bm, bn, M, N, K, 0, tid);

#pragma unroll 1
    for (int t = 0; t < nt; t++) {
        asm volatile("cp.async.wait_group 0;" ::: "memory");
        __syncthreads();
        if (t + 1 < nt)
            gemm_issue_tile(As, Bs, (t + 1) & 1, A, B, bm, bn, M, N, K, (t + 1) * 16, tid);

        int buf = t & 1;
#pragma unroll
        for (int ks = 0; ks < 2; ks++) {
            int k0 = ks * 8;
            unsigned af[2][4];
#pragma unroll
            for (int mi = 0; mi < 2; mi++) {
                int m0 = warp_m * 32 + mi * 16 + gr;
                af[mi][0] = __float_as_uint(As[buf][m0][k0 + gc]);
                af[mi][1] = __float_as_uint(As[buf][m0 + 8][k0 + gc]);
                af[mi][2] = __float_as_uint(As[buf][m0][k0 + gc + 4]);
                af[mi][3] = __float_as_uint(As[buf][m0 + 8][k0 + gc + 4]);
            }
            unsigned bf[8][2];
#pragma unroll
            for (int ni = 0; ni < 8; ni++) {
                int n0 = warp_n * 64 + ni * 8 + gr;
                bf[ni][0] = __float_as_uint(Bs[buf][k0 + gc][n0]);
                bf[ni][1] = __float_as_uint(Bs[buf][k0 + gc + 4][n0]);
            }
#pragma unroll
            for (int mi = 0; mi < 2; mi++)
#pragma unroll
                for (int ni = 0; ni < 8; ni++) {
                    asm volatile(
                        "mma.sync.aligned.m16n8k8.row.col.f32.tf32.tf32.f32 "
                        "{%0,%1,%2,%3}, {%4,%5,%6,%7}, {%8,%9}, {%0,%1,%2,%3};"
                        : "+f"(acc[mi][ni][0]), "+f"(acc[mi][ni][1]),
                          "+f"(acc[mi][ni][2]), "+f"(acc[mi][ni][3])
                        : "r"(af[mi][0]), "r"(af[mi][1]), "r"(af[mi][2]), "r"(af[mi][3]),
                          "r"(bf[ni][0]), "r"(bf[ni][1]));
                }
        }
        __syncthreads();
    }

#pragma unroll
    for (int mi = 0; mi < 2; mi++) {
#pragma unroll
        for (int ni = 0; ni < 8; ni++) {
            int r0 = bm + warp_m * 32 + mi * 16 + gr;
            int cn = bn + warp_n * 64 + ni * 8 + gc * 2;
            if (r0 < M) {
                float2 v = make_float2(acc[mi][ni][0], acc[mi][ni][1]);
                *(float2*)(C + (size_t)r0 * N + cn) = v;
            }
            if (r0 + 8 < M) {
                float2 v = make_float2(acc[mi][ni][2], acc[mi][ni][3]);
                *(float2*)(C + (size_t)(r0 + 8) * N + cn) = v;
            }
        }
    }
}

// ---------------- SIMT SGEMM (classifier only, N=153) ----------------
__global__ __launch_bounds__(256) void k_sgemm(
    const float* __restrict__ A, const float* __restrict__ B,
    float* __restrict__ C, int M, int N, int K,
    const float* __restrict__ bias)
{
    __shared__ float As[8][128];
    __shared__ float Bs[8][128];

    int tid = threadIdx.x;
    int bm = blockIdx.y * 128;
    int bn = blockIdx.x * 128;

    int aRow = tid >> 1;
    int aCol = (tid & 1) * 4;
    int bRow = tid >> 5;
    int bCol = (tid & 31) * 4;

    int tr = (tid >> 4) * 8;
    int tc = (tid & 15) * 8;

    float acc[8][8];
#pragma unroll
    for (int i = 0; i < 8; i++)
#pragma unroll
        for (int j = 0; j < 8; j++) acc[i][j] = 0.0f;

    bool aValid = (bm + aRow) < M;
    const float* Ap = A + (size_t)(bm + aRow) * K + aCol;
    bool nAligned = (N & 3) == 0;
    bool bFull = (bn + bCol + 3) < N;

    for (int k0 = 0; k0 < K; k0 += 8) {
        float4 a4 = make_float4(0.f, 0.f, 0.f, 0.f);
        if (aValid) a4 = *(const float4*)(Ap + k0);

        const float* bsrc = B + (size_t)(k0 + bRow) * N + bn + bCol;
        float4 b4;
        if (nAligned && bFull) {
            b4 = *(const float4*)bsrc;
        } else {
            b4.x = (bn + bCol + 0) < N ? bsrc[0] : 0.f;
            b4.y = (bn + bCol + 1) < N ? bsrc[1] : 0.f;
            b4.z = (bn + bCol + 2) < N ? bsrc[2] : 0.f;
            b4.w = (bn + bCol + 3) < N ? bsrc[3] : 0.f;
        }

        __syncthreads();
        As[aCol + 0][aRow] = a4.x;
        As[aCol + 1][aRow] = a4.y;
        As[aCol + 2][aRow] = a4.z;
        As[aCol + 3][aRow] = a4.w;
        *(float4*)&Bs[bRow][bCol] = b4;
        __syncthreads();

#pragma unroll
        for (int k = 0; k < 8; k++) {
            float ar_[8], br_[8];
#pragma unroll
            for (int i = 0; i < 8; i++) ar_[i] = As[k][tr + i];
#pragma unroll
            for (int j = 0; j < 8; j++) br_[j] = Bs[k][tc + j];
#pragma unroll
            for (int i = 0; i < 8; i++)
#pragma unroll
                for (int j = 0; j < 8; j++)
                    acc[i][j] = fmaf(ar_[i], br_[j], acc[i][j]);
        }
    }

#pragma unroll
    for (int i = 0; i < 8; i++) {
        int r = bm + tr + i;
        if (r >= M) continue;
#pragma unroll
        for (int j = 0; j < 8; j++) {
            int c = bn + tc + j;
            if (c < N) {
                float v = acc[i][j];
                if (bias) v += bias[c];
                C[(size_t)r * N + c] = v;
            }
        }
    }
}

// ---------------- attention logit dots ----------------
__global__ void k_dots(const float* __restrict__ Z,
                       const float* __restrict__ al, const float* __restrict__ ar,
                       float* __restrict__ el, float* __restrict__ er, int Nn)
{
    int warp = (blockIdx.x * blockDim.x + threadIdx.x) >> 5;
    int lane = threadIdx.x & 31;
    if (warp >= Nn) return;
    const float4* zp = (const float4*)Z + (size_t)warp * 128;
    const float4* alp = (const float4*)al;
    const float4* arp = (const float4*)ar;
    float sl[4], sr[4];
#pragma unroll
    for (int i = 0; i < 4; i++) {
        float4 z = zp[i * 32 + lane];
        float4 a = alp[i * 32 + lane];
        float4 r = arp[i * 32 + lane];
        sl[i] = z.x * a.x + z.y * a.y + z.z * a.z + z.w * a.w;
        sr[i] = z.x * r.x + z.y * r.y + z.z * r.z + z.w * r.w;
    }
#pragma unroll
    for (int off = 16; off > 0; off >>= 1) {
#pragma unroll
        for (int i = 0; i < 4; i++) {
            sl[i] += __shfl_down_sync(0xffffffffu, sl[i], off);
            sr[i] += __shfl_down_sync(0xffffffffu, sr[i], off);
        }
    }
    if (lane == 0) {
#pragma unroll
        for (int i = 0; i < 4; i++) {
            el[warp * 4 + i] = sl[i];
            er[warp * 4 + i] = sr[i];
        }
    }
}

// ---------------- fused per-dst GAT aggregation (CSR) ----------------
__device__ __forceinline__ float leaky02(float v) { return v > 0.f ? v : 0.2f * v; }

__global__ void k_gat_csr(const int* __restrict__ off, const int* __restrict__ eid,
                          const int* __restrict__ src,
                          const float* __restrict__ el, const float* __restrict__ er,
                          const float* __restrict__ Z, float* __restrict__ out,
                          int nDst, int accumulate, int dorelu)
{
    int w = (blockIdx.x * blockDim.x + threadIdx.x) >> 5;
    if (w >= nDst) return;
    int lane = threadIdx.x & 31;
    int beg = off[w], end = off[w + 1];

    float4 accv[4];
    float4* op = (float4*)out + (size_t)w * 128;
    if (accumulate) {
#pragma unroll
        for (int j = 0; j < 4; j++) accv[j] = op[j * 32 + lane];
    } else {
#pragma unroll
        for (int j = 0; j < 4; j++) accv[j] = make_float4(0.f, 0.f, 0.f, 0.f);
    }

    if (beg < end) {
        float4 r4 = ((const float4*)er)[w];

        // pass 1: max over edges
        float m[4] = {-1e30f, -1e30f, -1e30f, -1e30f};
        for (int i = beg + lane; i < end; i += 32) {
            int sn = src[eid[i]];
            float4 e4 = ((const float4*)el)[sn];
            m[0] = fmaxf(m[0], leaky02(e4.x + r4.x));
            m[1] = fmaxf(m[1], leaky02(e4.y + r4.y));
            m[2] = fmaxf(m[2], leaky02(e4.z + r4.z));
            m[3] = fmaxf(m[3], leaky02(e4.w + r4.w));
        }
#pragma unroll
        for (int o = 16; o > 0; o >>= 1) {
#pragma unroll
            for (int k = 0; k < 4; k++)
                m[k] = fmaxf(m[k], __shfl_xor_sync(0xffffffffu, m[k], o));
        }

        // pass 2: sum of exp
        float s[4] = {0.f, 0.f, 0.f, 0.f};
        for (int i = beg + lane; i < end; i += 32) {
            int sn = src[eid[i]];
            float4 e4 = ((const float4*)el)[sn];
            s[0] += expf(leaky02(e4.x + r4.x) - m[0]);
            s[1] += expf(leaky02(e4.y + r4.y) - m[1]);
            s[2] += expf(leaky02(e4.z + r4.z) - m[2]);
            s[3] += expf(leaky02(e4.w + r4.w) - m[3]);
        }
#pragma unroll
        for (int o = 16; o > 0; o >>= 1) {
#pragma unroll
            for (int k = 0; k < 4; k++)
                s[k] += __shfl_xor_sync(0xffffffffu, s[k], o);
        }
        float inv[4];
#pragma unroll
        for (int k = 0; k < 4; k++) inv[k] = 1.0f / (s[k] + 1e-9f);

        // pass 3: weighted aggregation (full warp per edge row)
        for (int i = beg; i < end; i++) {
            int sn = src[eid[i]];
            float4 e4 = ((const float4*)el)[sn];
            float a0 = expf(leaky02(e4.x + r4.x) - m[0]) * inv[0];
            float a1 = expf(leaky02(e4.y + r4.y) - m[1]) * inv[1];
            float a2 = expf(leaky02(e4.z + r4.z) - m[2]) * inv[2];
            float a3 = expf(leaky02(e4.w + r4.w) - m[3]) * inv[3];
            const float4* zp = (const float4*)Z + (size_t)sn * 128;
            float4 z0 = zp[0 * 32 + lane];
            float4 z1 = zp[1 * 32 + lane];
            float4 z2 = zp[2 * 32 + lane];
            float4 z3 = zp[3 * 32 + lane];
            accv[0].x += a0 * z0.x; accv[0].y += a0 * z0.y;
            accv[0].z += a0 * z0.z; accv[0].w += a0 * z0.w;
            accv[1].x += a1 * z1.x; accv[1].y += a1 * z1.y;
            accv[1].z += a1 * z1.z; accv[1].w += a1 * z1.w;
            accv[2].x += a2 * z2.x; accv[2].y += a2 * z2.y;
            accv[2].z += a2 * z2.z; accv[2].w += a2 * z2.w;
            accv[3].x += a3 * z3.x; accv[3].y += a3 * z3.y;
            accv[3].z += a3 * z3.z; accv[3].w += a3 * z3.w;
        }
    }

    if (dorelu) {
#pragma unroll
        for (int j = 0; j < 4; j++) {
            accv[j].x = fmaxf(accv[j].x, 0.f);
            accv[j].y = fmaxf(accv[j].y, 0.f);
            accv[j].z = fmaxf(accv[j].z, 0.f);
            accv[j].w = fmaxf(accv[j].w, 0.f);
        }
    }
#pragma unroll
    for (int j = 0; j < 4; j++) op[j * 32 + lane] = accv[j];
}

// ---------------- host-side launch helpers ----------------
static inline void launch_gemm_tf32(const float* A, const float* B, float* C, int M, int K)
{
    dim3 grid(HIDDEN / 128, (M + 127) / 128);
    k_tf32_gemm<<<grid, 256>>>(A, B, C, M, HIDDEN, K);
}

static inline void launch_gemm_simt(const float* A, const float* B, float* C,
                                    int M, int N, int K, const float* bias)
{
    dim3 grid((N + 127) / 128, (M + 127) / 128);
    k_sgemm<<<grid, 256>>>(A, B, C, M, N, K, bias);
}

static inline void launch_cvt(const float* in, float* out, size_t n)
{
    int n4 = (int)(n / 4);
    int blocks = (n4 + 255) / 256;
    if (blocks > 2048) blocks = 2048;
    k_cvt_tf32<<<blocks, 256>>>(in, out, n4);
}

static inline void launch_dots(const float* Z, const float* al, const float* ar,
                               float* el, float* er, int Nn)
{
    int threads = Nn * 32;
    k_dots<<<(threads + 255) / 256, 256>>>(Z, al, ar, el, er, Nn);
}

static inline void build_csr(const int* dst, int E, int nDst,
                             int* cnt, int* off, int* eid)
{
    k_izero<<<(nDst + 255) / 256, 256>>>(cnt, nDst);
    k_hist<<<(E + 255) / 256, 256>>>(dst, E, cnt);
    k_scan<<<1, 1024>>>(cnt, off, nDst);
    k_izero<<<(nDst + 255) / 256, 256>>>(cnt, nDst);
    k_scatter<<<(E + 255) / 256, 256>>>(dst, E, off, cnt, eid);
}

static inline void launch_gat(const int* off, const int* eid, const int* src,
                              const float* el, const float* er,
                              const float* Z, float* out,
                              int nDst, int accumulate, int dorelu)
{
    int threads = nDst * 32;
    k_gat_csr<<<(threads + 255) / 256, 256>>>(off, eid, src, el, er, Z, out,
                                              nDst, accumulate, dorelu);
}

extern "C" void kernel_launch(void* const* d_in, const int* in_sizes, int n_in,
                              void* d_out, int out_size)
{
    const float* x_paper  = (const float*)d_in[0];
    const float* x_author = (const float*)d_in[1];
    const int* cs = (const int*)d_in[2];
    const int* cd = (const int*)d_in[3];
    const int* ws = (const int*)d_in[4];
    const int* wd = (const int*)d_in[5];
    const int* bsrc = (const int*)d_in[6];
    const int* bdst = (const int*)d_in[7];
    const float* Wt[3] = { (const float*)d_in[8],  (const float*)d_in[11], (const float*)d_in[14] };
    const float* AL[3] = { (const float*)d_in[9],  (const float*)d_in[12], (const float*)d_in[15] };
    const float* AR[3] = { (const float*)d_in[10], (const float*)d_in[13], (const float*)d_in[16] };
    const float* linW = (const float*)d_in[17];
    const float* linb = (const float*)d_in[18];
    float* out = (float*)d_out;

    float *ZP0, *ZP1, *ZP2, *ZA1, *ZA2, *OP, *OA, *Ap, *Aa, *Wc;
    float *elc, *erc, *elw, *erw, *elb, *erb, *jp, *ja;
    int *cnt, *offc, *offw, *offb, *eidc, *eidw, *eidb;
    cudaGetSymbolAddress((void**)&ZP0, g_ZP0);
    cudaGetSymbolAddress((void**)&ZP1, g_ZP1);
    cudaGetSymbolAddress((void**)&ZP2, g_ZP2);
    cudaGetSymbolAddress((void**)&ZA1, g_ZA1);
    cudaGetSymbolAddress((void**)&ZA2, g_ZA2);
    cudaGetSymbolAddress((void**)&OP,  g_OP);
    cudaGetSymbolAddress((void**)&OA,  g_OA);
    cudaGetSymbolAddress((void**)&Ap,  g_Ap);
    cudaGetSymbolAddress((void**)&Aa,  g_Aa);
    cudaGetSymbolAddress((void**)&Wc,  g_Wc);
    cudaGetSymbolAddress((void**)&elc, g_elc);
    cudaGetSymbolAddress((void**)&erc, g_erc);
    cudaGetSymbolAddress((void**)&elw, g_elw);
    cudaGetSymbolAddress((void**)&erw, g_erw);
    cudaGetSymbolAddress((void**)&elb, g_elb);
    cudaGetSymbolAddress((void**)&erb, g_erb);
    cudaGetSymbolAddress((void**)&jp,  g_jp);
    cudaGetSymbolAddress((void**)&ja,  g_ja);
    cudaGetSymbolAddress((void**)&cnt,  g_cnt);
    cudaGetSymbolAddress((void**)&offc, g_offc);
    cudaGetSymbolAddress((void**)&offw, g_offw);
    cudaGetSymbolAddress((void**)&offb, g_offb);
    cudaGetSymbolAddress((void**)&eidc, g_eidc);
    cudaGetSymbolAddress((void**)&eidw, g_eidw);
    cudaGetSymbolAddress((void**)&eidb, g_eidb);

    // CSR for the three edge types (reused across layers)
    build_csr(cd,   NEC,  NPAPER, cnt, offc, eidc);
    build_csr(wd,   NEW_, NPAPER, cnt, offw, eidw);
    build_csr(bdst, NEB,  NAUTH,  cnt, offb, eidb);

    for (int L = 0; L < 3; ++L) {
        const float* hp = (L == 0) ? x_paper  : OP;
        const float* ha = (L == 0) ? x_author : OA;
        int K = (L == 0) ? 1024 : 512;
        const float* al = AL[L];
        const float* ar = AR[L];
        size_t wstride = (size_t)K * HIDDEN;
        int relu = (L < 2) ? 1 : 0;

        // pre-convert activations + weights to tf32 (rna)
        launch_cvt(hp, Ap, (size_t)NPAPER * K);
        launch_cvt(ha, Aa, (size_t)NAUTH * K);
        launch_cvt(Wt[L], Wc, (size_t)3 * K * HIDDEN);

        // z = h @ W per (node type, relation)
        launch_gemm_tf32(Ap, Wc + 0 * wstride, ZP0, NPAPER, K);
        launch_gemm_tf32(Ap, Wc + 1 * wstride, ZP1, NPAPER, K);
        launch_gemm_tf32(Ap, Wc + 2 * wstride, ZP2, NPAPER, K);
        launch_gemm_tf32(Aa, Wc + 1 * wstride, ZA1, NAUTH, K);
        launch_gemm_tf32(Aa, Wc + 2 * wstride, ZA2, NAUTH, K);

        // attention logits
        launch_dots(ZP0, al + 0,    ar + 0,    elc, erc, NPAPER);
        launch_dots(ZA1, al + 512,  ar + 512,  elw, ja,  NAUTH);
        launch_dots(ZP1, al + 512,  ar + 512,  jp,  erw, NPAPER);
        launch_dots(ZP2, al + 1024, ar + 1024, elb, jp,  NPAPER);
        launch_dots(ZA2, al + 1024, ar + 1024, ja,  erb, NAUTH);

        // fused softmax + aggregation per destination (CSR)
        launch_gat(offc, eidc, cs,   elc, erc, ZP0, OP, NPAPER, 0, 0);
        launch_gat(offw, eidw, ws,   elw, erw, ZA1, OP, NPAPER, 1, relu);
        launch_gat(offb, eidb, bsrc, elb, erb, ZP2, OA, NAUTH,  0, relu);
    }

    // classifier: out = hp_final @ linW + linb
    launch_gemm_simt(OP, linW, out, NPAPER, NCLS, HIDDEN, linb);
}

// round 8
// speedup vs baseline: 3.3578x; 1.2194x over previous
#include <cuda_runtime.h>
#include <cstdint>

#define NPAPER 60000
#define NAUTH  30000
#define NEC    300000
#define NEW_   150000
#define NEB    150000
#define HIDDEN 512
#define NCLS   153

// ---------------- scratch (device globals; no allocation allowed) ----------------
__device__ float g_ZP [(size_t)NPAPER * 1536];   // packed paper projections (up to 3 relations)
__device__ float g_ZA [(size_t)NAUTH  * 1024];   // packed author projections (up to 2 relations)
__device__ float g_OP [(size_t)NPAPER * HIDDEN];
__device__ float g_OA [(size_t)NAUTH * HIDDEN];
__device__ float g_Ap [(size_t)NPAPER * 1024];   // tf32 layer-0 paper features / classifier scratch
__device__ float g_Aa [(size_t)NAUTH  * 1024];   // tf32 layer-0 author features
__device__ float g_Wp [(size_t)1024 * 1536];     // packed tf32 paper weights
__device__ float g_Wa [(size_t)1024 * 1024];     // packed tf32 author weights
__device__ float g_lin[512 * 256];               // padded tf32 classifier weights
__device__ float g_elc[NPAPER * 4];
__device__ float g_erc[NPAPER * 4];
__device__ float g_elw[NAUTH  * 4];
__device__ float g_erw[NPAPER * 4];
__device__ float g_elb[NPAPER * 4];
__device__ float g_erb[NAUTH  * 4];
__device__ float g_jp [NPAPER * 4];
__device__ float g_ja [NAUTH  * 4];
// CSR scratch
__device__ int g_cnt [NPAPER];
__device__ int g_offc[NPAPER + 1];
__device__ int g_offw[NPAPER + 1];
__device__ int g_offb[NAUTH + 1];
__device__ int g_eidc[NEC];
__device__ int g_eidw[NEW_];
__device__ int g_eidb[NEB];

// ---------------- helpers ----------------
__device__ __forceinline__ float rna_tf32(float f) {
    unsigned u;
    asm("cvt.rna.tf32.f32 %0, %1;" : "=r"(u) : "f"(f));
    return __uint_as_float(u);
}

__global__ void k_izero(int* __restrict__ p, int n) {
    int i = blockIdx.x * blockDim.x + threadIdx.x;
    int stride = gridDim.x * blockDim.x;
    for (; i < n; i += stride) p[i] = 0;
}

// tf32 pre-conversion of fp32 input, n4 = count/4
__global__ void k_cvt_tf32(const float* __restrict__ in, float* __restrict__ out, int n4) {
    int i = blockIdx.x * blockDim.x + threadIdx.x;
    int stride = gridDim.x * blockDim.x;
    for (; i < n4; i += stride) {
        float4 v = ((const float4*)in)[i];
        v.x = rna_tf32(v.x); v.y = rna_tf32(v.y);
        v.z = rna_tf32(v.z); v.w = rna_tf32(v.w);
        ((float4*)out)[i] = v;
    }
}

// pack weights W[(3,K,512)] relations [r0, r0+nrel) -> out[k][(q*512)+n], tf32
__global__ void k_pack_w(const float* __restrict__ W, float* __restrict__ out,
                         int K, int r0, int nrel) {
    int total = K * nrel * 128;  // float4 count
    int i = blockIdx.x * blockDim.x + threadIdx.x;
    int stride = gridDim.x * blockDim.x;
    for (; i < total; i += stride) {
        int n4 = i & 127;
        int kq = i >> 7;
        int q = kq % nrel, k = kq / nrel;
        float4 v = ((const float4*)(W + ((size_t)(r0 + q) * K + k) * 512))[n4];
        v.x = rna_tf32(v.x); v.y = rna_tf32(v.y);
        v.z = rna_tf32(v.z); v.w = rna_tf32(v.w);
        ((float4*)(out + ((size_t)k * nrel + q) * 512))[n4] = v;
    }
}

// pack classifier weights [512,153] -> [512,256] zero-padded tf32
__global__ void k_pack_lin(const float* __restrict__ linW, float* __restrict__ out) {
    int i = blockIdx.x * blockDim.x + threadIdx.x;
    if (i >= 512 * 256) return;
    int k = i >> 8, c = i & 255;
    out[i] = (c < NCLS) ? rna_tf32(linW[k * NCLS + c]) : 0.0f;
}

// copy padded classifier output [M,256] -> out [M,153] + bias
__global__ void k_bias_out(const float* __restrict__ CO, const float* __restrict__ bias,
                           float* __restrict__ out, int M) {
    int i = blockIdx.x * blockDim.x + threadIdx.x;
    int stride = gridDim.x * blockDim.x;
    int total = M * NCLS;
    for (; i < total; i += stride) {
        int r = i / NCLS, c = i - r * NCLS;
        out[i] = CO[(size_t)r * 256 + c] + bias[c];
    }
}

// ---------------- CSR build: histogram / scan / scatter ----------------
__global__ void k_hist(const int* __restrict__ dst, int E, int* __restrict__ cnt) {
    int e = blockIdx.x * blockDim.x + threadIdx.x;
    if (e < E) atomicAdd(&cnt[dst[e]], 1);
}

__global__ void k_scan(const int* __restrict__ cnt, int* __restrict__ off, int n) {
    __shared__ int sh[1024];
    int tid = threadIdx.x;
    int C = (n + 1023) / 1024;
    int b = tid * C;
    int sum = 0;
    for (int i = 0; i < C; i++)
        if (b + i < n) sum += cnt[b + i];
    sh[tid] = sum;
    __syncthreads();
    for (int d = 1; d < 1024; d <<= 1) {
        int t = 0;
        if (tid >= d) t = sh[tid - d];
        __syncthreads();
        if (tid >= d) sh[tid] += t;
        __syncthreads();
    }
    int run = sh[tid] - sum;
    for (int i = 0; i < C; i++) {
        if (b + i < n) { off[b + i] = run; run += cnt[b + i]; }
    }
    if (tid == 1023) off[n] = sh[1023];
}

__global__ void k_scatter(const int* __restrict__ dst, int E,
                          const int* __restrict__ off, int* __restrict__ cur,
                          int* __restrict__ eid) {
    int e = blockIdx.x * blockDim.x + threadIdx.x;
    if (e >= E) return;
    int d = dst[e];
    int p = off[d] + atomicAdd(&cur[d], 1);
    eid[p] = e;
}

// ---------------- TF32 tensor-core GEMM (mma.sync), cp.async loads ----------------
// C[M,N] = A[M,K] @ B[K,N], row-major, N % 128 == 0, K % 16 == 0, inputs tf32-rounded.
#define AS_STRIDE 20
#define BS_STRIDE 136

__device__ __forceinline__ uint32_t smem_u32(const void* p) {
    uint32_t a;
    asm("{ .reg .u64 t; cvta.to.shared.u64 t, %1; cvt.u32.u64 %0, t; }" : "=r"(a) : "l"(p));
    return a;
}

__device__ __forceinline__ void cp16(uint32_t s, const float* g, bool v) {
    asm volatile("cp.async.cg.shared.global [%0], [%1], 16, %2;"
                 :: "r"(s), "l"(__cvta_generic_to_global(g)), "r"(v ? 16 : 0));
}

__device__ __forceinline__ void gemm_issue_tile(
    float (*As)[128][AS_STRIDE], float (*Bs)[16][BS_STRIDE],
    int buf, const float* __restrict__ A, const float* __restrict__ B,
    int bm, int bn, int M, int N, int K, int k0, int tid)
{
    int am = tid >> 2, ac4 = tid & 3;
    int bk = tid >> 5, bc4 = tid & 31;
#pragma unroll
    for (int i = 0; i < 2; i++) {
        int m = am + i * 64;
        int mm = bm + m;
        int msafe = mm < M ? mm : (M - 1);
        cp16(smem_u32(&As[buf][m][ac4 * 4]),
             A + (size_t)msafe * K + k0 + ac4 * 4, mm < M);
    }
#pragma unroll
    for (int i = 0; i < 2; i++) {
        int kr = bk + i * 8;
        cp16(smem_u32(&Bs[buf][kr][bc4 * 4]),
             B + (size_t)(k0 + kr) * N + bn + bc4 * 4, true);
    }
    asm volatile("cp.async.commit_group;" ::: "memory");
}

__global__ __launch_bounds__(256) void k_tf32_gemm(
    const float* __restrict__ A, const float* __restrict__ B,
    float* __restrict__ C, int M, int N, int K)
{
    __shared__ float As[2][128][AS_STRIDE];
    __shared__ float Bs[2][16][BS_STRIDE];

    int tid = threadIdx.x;
    int lane = tid & 31;
    int wid = tid >> 5;
    int warp_m = wid & 3;
    int warp_n = wid >> 2;
    int gr = lane >> 2;
    int gc = lane & 3;

    int bm = blockIdx.y * 128;
    int bn = blockIdx.x * 128;

    float acc[2][8][4];
#pragma unroll
    for (int mi = 0; mi < 2; mi++)
#pragma unroll
        for (int ni = 0; ni < 8; ni++)
#pragma unroll
            for (int j = 0; j < 4; j++) acc[mi][ni][j] = 0.0f;

    int nt = K >> 4;

    gemm_issue_tile(As, Bs, 0, A, B, bm, bn, M, N, K, 0, tid);

#pragma unroll 1
    for (int t = 0; t < nt; t++) {
        asm volatile("cp.async.wait_group 0;" ::: "memory");
        __syncthreads();
        if (t + 1 < nt)
            gemm_issue_tile(As, Bs, (t + 1) & 1, A, B, bm, bn, M, N, K, (t + 1) * 16, tid);

        int buf = t & 1;
#pragma unroll
        for (int ks = 0; ks < 2; ks++) {
            int k0 = ks * 8;
            unsigned af[2][4];
#pragma unroll
            for (int mi = 0; mi < 2; mi++) {
                int m0 = warp_m * 32 + mi * 16 + gr;
                af[mi][0] = __float_as_uint(As[buf][m0][k0 + gc]);
                af[mi][1] = __float_as_uint(As[buf][m0 + 8][k0 + gc]);
                af[mi][2] = __float_as_uint(As[buf][m0][k0 + gc + 4]);
                af[mi][3] = __float_as_uint(As[buf][m0 + 8][k0 + gc + 4]);
            }
            unsigned bf[8][2];
#pragma unroll
            for (int ni = 0; ni < 8; ni++) {
                int n0 = warp_n * 64 + ni * 8 + gr;
                bf[ni][0] = __float_as_uint(Bs[buf][k0 + gc][n0]);
                bf[ni][1] = __float_as_uint(Bs[buf][k0 + gc + 4][n0]);
            }
#pragma unroll
            for (int mi = 0; mi < 2; mi++)
#pragma unroll
                for (int ni = 0; ni < 8; ni++) {
                    asm volatile(
                        "mma.sync.aligned.m16n8k8.row.col.f32.tf32.tf32.f32 "
                        "{%0,%1,%2,%3}, {%4,%5,%6,%7}, {%8,%9}, {%0,%1,%2,%3};"
                        : "+f"(acc[mi][ni][0]), "+f"(acc[mi][ni][1]),
                          "+f"(acc[mi][ni][2]), "+f"(acc[mi][ni][3])
                        : "r"(af[mi][0]), "r"(af[mi][1]), "r"(af[mi][2]), "r"(af[mi][3]),
                          "r"(bf[ni][0]), "r"(bf[ni][1]));
                }
        }
        __syncthreads();
    }

#pragma unroll
    for (int mi = 0; mi < 2; mi++) {
#pragma unroll
        for (int ni = 0; ni < 8; ni++) {
            int r0 = bm + warp_m * 32 + mi * 16 + gr;
            int cn = bn + warp_n * 64 + ni * 8 + gc * 2;
            if (r0 < M) {
                float2 v = make_float2(acc[mi][ni][0], acc[mi][ni][1]);
                *(float2*)(C + (size_t)r0 * N + cn) = v;
            }
            if (r0 + 8 < M) {
                float2 v = make_float2(acc[mi][ni][2], acc[mi][ni][3]);
                *(float2*)(C + (size_t)(r0 + 8) * N + cn) = v;
            }
        }
    }
}

// ---------------- attention logit dots (strided Z) ----------------
__global__ void k_dots(const float* __restrict__ Z, int zs4,
                       const float* __restrict__ al, const float* __restrict__ ar,
                       float* __restrict__ el, float* __restrict__ er, int Nn)
{
    int warp = (blockIdx.x * blockDim.x + threadIdx.x) >> 5;
    int lane = threadIdx.x & 31;
    if (warp >= Nn) return;
    const float4* zp = (const float4*)Z + (size_t)warp * zs4;
    const float4* alp = (const float4*)al;
    const float4* arp = (const float4*)ar;
    float sl[4], sr[4];
#pragma unroll
    for (int i = 0; i < 4; i++) {
        float4 z = zp[i * 32 + lane];
        float4 a = alp[i * 32 + lane];
        float4 r = arp[i * 32 + lane];
        sl[i] = z.x * a.x + z.y * a.y + z.z * a.z + z.w * a.w;
        sr[i] = z.x * r.x + z.y * r.y + z.z * r.z + z.w * r.w;
    }
#pragma unroll
    for (int off = 16; off > 0; off >>= 1) {
#pragma unroll
        for (int i = 0; i < 4; i++) {
            sl[i] += __shfl_down_sync(0xffffffffu, sl[i], off);
            sr[i] += __shfl_down_sync(0xffffffffu, sr[i], off);
        }
    }
    if (lane == 0) {
#pragma unroll
        for (int i = 0; i < 4; i++) {
            el[warp * 4 + i] = sl[i];
            er[warp * 4 + i] = sr[i];
        }
    }
}

// ---------------- fused per-dst GAT aggregation (CSR, strided Z) ----------------
__device__ __forceinline__ float leaky02(float v) { return v > 0.f ? v : 0.2f * v; }

__global__ void k_gat_csr(const int* __restrict__ off, const int* __restrict__ eid,
                          const int* __restrict__ src,
                          const float* __restrict__ el, const float* __restrict__ er,
                          const float* __restrict__ Z, int zs4, float* __restrict__ out,
                          int nDst, int accumulate, int dorelu, int doround)
{
    int w = (blockIdx.x * blockDim.x + threadIdx.x) >> 5;
    if (w >= nDst) return;
    int lane = threadIdx.x & 31;
    int beg = off[w], end = off[w + 1];

    float4 accv[4];
    float4* op = (float4*)out + (size_t)w * 128;
    if (accumulate) {
#pragma unroll
        for (int j = 0; j < 4; j++) accv[j] = op[j * 32 + lane];
    } else {
#pragma unroll
        for (int j = 0; j < 4; j++) accv[j] = make_float4(0.f, 0.f, 0.f, 0.f);
    }

    if (beg < end) {
        float4 r4 = ((const float4*)er)[w];

        float m[4] = {-1e30f, -1e30f, -1e30f, -1e30f};
        for (int i = beg + lane; i < end; i += 32) {
            int sn = src[eid[i]];
            float4 e4 = ((const float4*)el)[sn];
            m[0] = fmaxf(m[0], leaky02(e4.x + r4.x));
            m[1] = fmaxf(m[1], leaky02(e4.y + r4.y));
            m[2] = fmaxf(m[2], leaky02(e4.z + r4.z));
            m[3] = fmaxf(m[3], leaky02(e4.w + r4.w));
        }
#pragma unroll
        for (int o = 16; o > 0; o >>= 1) {
#pragma unroll
            for (int k = 0; k < 4; k++)
                m[k] = fmaxf(m[k], __shfl_xor_sync(0xffffffffu, m[k], o));
        }

        float s[4] = {0.f, 0.f, 0.f, 0.f};
        for (int i = beg + lane; i < end; i += 32) {
            int sn = src[eid[i]];
            float4 e4 = ((const float4*)el)[sn];
            s[0] += expf(leaky02(e4.x + r4.x) - m[0]);
            s[1] += expf(leaky02(e4.y + r4.y) - m[1]);
            s[2] += expf(leaky02(e4.z + r4.z) - m[2]);
            s[3] += expf(leaky02(e4.w + r4.w) - m[3]);
        }
#pragma unroll
        for (int o = 16; o > 0; o >>= 1) {
#pragma unroll
            for (int k = 0; k < 4; k++)
                s[k] += __shfl_xor_sync(0xffffffffu, s[k], o);
        }
        float inv[4];
#pragma unroll
        for (int k = 0; k < 4; k++) inv[k] = 1.0f / (s[k] + 1e-9f);

        for (int i = beg; i < end; i++) {
            int sn = src[eid[i]];
            float4 e4 = ((const float4*)el)[sn];
            float a0 = expf(leaky02(e4.x + r4.x) - m[0]) * inv[0];
            float a1 = expf(leaky02(e4.y + r4.y) - m[1]) * inv[1];
            float a2 = expf(leaky02(e4.z + r4.z) - m[2]) * inv[2];
            float a3 = expf(leaky02(e4.w + r4.w) - m[3]) * inv[3];
            const float4* zp = (const float4*)Z + (size_t)sn * zs4;
            float4 z0 = zp[0 * 32 + lane];
            float4 z1 = zp[1 * 32 + lane];
            float4 z2 = zp[2 * 32 + lane];
            float4 z3 = zp[3 * 32 + lane];
            accv[0].x += a0 * z0.x; accv[0].y += a0 * z0.y;
            accv[0].z += a0 * z0.z; accv[0].w += a0 * z0.w;
            accv[1].x += a1 * z1.x; accv[1].y += a1 * z1.y;
            accv[1].z += a1 * z1.z; accv[1].w += a1 * z1.w;
            accv[2].x += a2 * z2.x; accv[2].y += a2 * z2.y;
            accv[2].z += a2 * z2.z; accv[2].w += a2 * z2.w;
            accv[3].x += a3 * z3.x; accv[3].y += a3 * z3.y;
            accv[3].z += a3 * z3.z; accv[3].w += a3 * z3.w;
        }
    }

    if (dorelu) {
#pragma unroll
        for (int j = 0; j < 4; j++) {
            accv[j].x = fmaxf(accv[j].x, 0.f);
            accv[j].y = fmaxf(accv[j].y, 0.f);
            accv[j].z = fmaxf(accv[j].z, 0.f);
            accv[j].w = fmaxf(accv[j].w, 0.f);
        }
    }
    if (doround) {
#pragma unroll
        for (int j = 0; j < 4; j++) {
            accv[j].x = rna_tf32(accv[j].x);
            accv[j].y = rna_tf32(accv[j].y);
            accv[j].z = rna_tf32(accv[j].z);
            accv[j].w = rna_tf32(accv[j].w);
        }
    }
#pragma unroll
    for (int j = 0; j < 4; j++) op[j * 32 + lane] = accv[j];
}

// ---------------- host-side launch helpers ----------------
static inline void launch_gemm_tf32(const float* A, const float* B, float* C,
                                    int M, int N, int K)
{
    dim3 grid(N / 128, (M + 127) / 128);
    k_tf32_gemm<<<grid, 256>>>(A, B, C, M, N, K);
}

static inline void launch_cvt(const float* in, float* out, size_t n)
{
    int n4 = (int)(n / 4);
    int blocks = (n4 + 255) / 256;
    if (blocks > 2048) blocks = 2048;
    k_cvt_tf32<<<blocks, 256>>>(in, out, n4);
}

static inline void launch_dots(const float* Z, int zs4, const float* al, const float* ar,
                               float* el, float* er, int Nn)
{
    int threads = Nn * 32;
    k_dots<<<(threads + 255) / 256, 256>>>(Z, zs4, al, ar, el, er, Nn);
}

static inline void build_csr(const int* dst, int E, int nDst,
                             int* cnt, int* off, int* eid)
{
    k_izero<<<(nDst + 255) / 256, 256>>>(cnt, nDst);
    k_hist<<<(E + 255) / 256, 256>>>(dst, E, cnt);
    k_scan<<<1, 1024>>>(cnt, off, nDst);
    k_izero<<<(nDst + 255) / 256, 256>>>(cnt, nDst);
    k_scatter<<<(E + 255) / 256, 256>>>(dst, E, off, cnt, eid);
}

static inline void launch_gat(const int* off, const int* eid, const int* src,
                              const float* el, const float* er,
                              const float* Z, int zs4, float* out,
                              int nDst, int accumulate, int dorelu, int doround)
{
    int threads = nDst * 32;
    k_gat_csr<<<(threads + 255) / 256, 256>>>(off, eid, src, el, er, Z, zs4, out,
                                              nDst, accumulate, dorelu, doround);
}

static inline void launch_pack_w(const float* W, float* out, int K, int r0, int nrel)
{
    int total = K * nrel * 128;
    int blocks = (total + 255) / 256;
    if (blocks > 2048) blocks = 2048;
    k_pack_w<<<blocks, 256>>>(W, out, K, r0, nrel);
}

extern "C" void kernel_launch(void* const* d_in, const int* in_sizes, int n_in,
                              void* d_out, int out_size)
{
    const float* x_paper  = (const float*)d_in[0];
    const float* x_author = (const float*)d_in[1];
    const int* cs = (const int*)d_in[2];
    const int* cd = (const int*)d_in[3];
    const int* ws = (const int*)d_in[4];
    const int* wd = (const int*)d_in[5];
    const int* bsrc = (const int*)d_in[6];
    const int* bdst = (const int*)d_in[7];
    const float* Wt[3] = { (const float*)d_in[8],  (const float*)d_in[11], (const float*)d_in[14] };
    const float* AL[3] = { (const float*)d_in[9],  (const float*)d_in[12], (const float*)d_in[15] };
    const float* AR[3] = { (const float*)d_in[10], (const float*)d_in[13], (const float*)d_in[16] };
    const float* linW = (const float*)d_in[17];
    const float* linb = (const float*)d_in[18];
    float* out = (float*)d_out;

    float *ZP, *ZA, *OP, *OA, *Ap, *Aa, *Wp, *Wa, *lin;
    float *elc, *erc, *elw, *erw, *elb, *erb, *jp, *ja;
    int *cnt, *offc, *offw, *offb, *eidc, *eidw, *eidb;
    cudaGetSymbolAddress((void**)&ZP,  g_ZP);
    cudaGetSymbolAddress((void**)&ZA,  g_ZA);
    cudaGetSymbolAddress((void**)&OP,  g_OP);
    cudaGetSymbolAddress((void**)&OA,  g_OA);
    cudaGetSymbolAddress((void**)&Ap,  g_Ap);
    cudaGetSymbolAddress((void**)&Aa,  g_Aa);
    cudaGetSymbolAddress((void**)&Wp,  g_Wp);
    cudaGetSymbolAddress((void**)&Wa,  g_Wa);
    cudaGetSymbolAddress((void**)&lin, g_lin);
    cudaGetSymbolAddress((void**)&elc, g_elc);
    cudaGetSymbolAddress((void**)&erc, g_erc);
    cudaGetSymbolAddress((void**)&elw, g_elw);
    cudaGetSymbolAddress((void**)&erw, g_erw);
    cudaGetSymbolAddress((void**)&elb, g_elb);
    cudaGetSymbolAddress((void**)&erb, g_erb);
    cudaGetSymbolAddress((void**)&jp,  g_jp);
    cudaGetSymbolAddress((void**)&ja,  g_ja);
    cudaGetSymbolAddress((void**)&cnt,  g_cnt);
    cudaGetSymbolAddress((void**)&offc, g_offc);
    cudaGetSymbolAddress((void**)&offw, g_offw);
    cudaGetSymbolAddress((void**)&offb, g_offb);
    cudaGetSymbolAddress((void**)&eidc, g_eidc);
    cudaGetSymbolAddress((void**)&eidw, g_eidw);
    cudaGetSymbolAddress((void**)&eidb, g_eidb);

    // CSR for the three edge types (reused across layers)
    build_csr(cd,   NEC,  NPAPER, cnt, offc, eidc);
    build_csr(wd,   NEW_, NPAPER, cnt, offw, eidw);
    build_csr(bdst, NEB,  NAUTH,  cnt, offb, eidb);

    // layer-0 activation conversion (later layers written tf32-rounded by GAT)
    launch_cvt(x_paper,  Ap, (size_t)NPAPER * 1024);
    launch_cvt(x_author, Aa, (size_t)NAUTH * 1024);

    for (int L = 0; L < 3; ++L) {
        const float* hp = (L == 0) ? Ap : OP;
        const float* ha = (L == 0) ? Aa : OA;
        int K = (L == 0) ? 1024 : 512;
        const float* al = AL[L];
        const float* ar = AR[L];
        int relu = (L < 2) ? 1 : 0;
        int last = (L == 2);

        // pack tf32 weights: papers need relations [0..nrp), authors [1..1+nra)
        int nrp = last ? 2 : 3;   // L2: paper dst needs rel 0 (cites) + rel 1 (writes) only
        int nra = last ? 1 : 2;   // L2: authors only as writes-src (rel 1)
        int Np = nrp * 512, Na = nra * 512;
        launch_pack_w(Wt[L], Wp, K, 0, nrp);
        launch_pack_w(Wt[L], Wa, K, 1, nra);

        // merged projections
        launch_gemm_tf32(hp, Wp, ZP, NPAPER, Np, K);
        launch_gemm_tf32(ha, Wa, ZA, NAUTH, Na, K);

        int zp4 = Np / 4, za4 = Na / 4;

        // attention logits
        launch_dots(ZP + 0,    zp4, al + 0,    ar + 0,    elc, erc, NPAPER); // cites
        launch_dots(ZA + 0,    za4, al + 512,  ar + 512,  elw, ja,  NAUTH);  // writes src
        launch_dots(ZP + 512,  zp4, al + 512,  ar + 512,  jp,  erw, NPAPER); // writes dst
        if (!last) {
            launch_dots(ZP + 1024, zp4, al + 1024, ar + 1024, elb, jp, NPAPER); // wb src
            launch_dots(ZA + 512,  za4, al + 1024, ar + 1024, ja, erb, NAUTH);  // wb dst
        }

        // fused softmax + aggregation per destination
        launch_gat(offc, eidc, cs, elc, erc, ZP + 0,   zp4, OP, NPAPER, 0, 0, 0);
        launch_gat(offw, eidw, ws, elw, erw, ZA + 0,   za4, OP, NPAPER, 1, relu, 1);
        if (!last)
            launch_gat(offb, eidb, bsrc, elb, erb, ZP + 1024, zp4, OA, NAUTH, 0, relu, 1);
    }

    // classifier: tf32 GEMM into padded scratch, then bias + copy-out
    k_pack_lin<<<(512 * 256 + 255) / 256, 256>>>(linW, lin);
    launch_gemm_tf32(OP, lin, Ap, NPAPER, 256, HIDDEN);
    {
        int total = NPAPER * NCLS;
        int blocks = (total + 255) / 256;
        if (blocks > 4096) blocks = 4096;
        k_bias_out<<<blocks, 256>>>(Ap, linb, out, NPAPER);
    }
}

// round 9
// speedup vs baseline: 3.4815x; 1.0368x over previous
#include <cuda_runtime.h>
#include <cstdint>

#define NPAPER 60000
#define NAUTH  30000
#define NEC    300000
#define NEW_   150000
#define NEB    150000
#define HIDDEN 512
#define NCLS   153

// ---------------- scratch (device globals; no allocation allowed) ----------------
__device__ float g_ZP [(size_t)NPAPER * 1536];
__device__ float g_ZA [(size_t)NAUTH  * 1024];
__device__ float g_OP [(size_t)NPAPER * HIDDEN];
__device__ float g_OA [(size_t)NAUTH * HIDDEN];
__device__ float g_Ap [(size_t)NPAPER * 1024];   // tf32 layer-0 paper feats / classifier scratch
__device__ float g_Aa [(size_t)NAUTH  * 1024];
__device__ float g_Wp [(size_t)1024 * 1536];
__device__ float g_Wa [(size_t)1024 * 1024];
__device__ float g_lin[512 * 256];
__device__ float g_elc[NPAPER * 4];
__device__ float g_erc[NPAPER * 4];
__device__ float g_elw[NAUTH  * 4];
__device__ float g_erw[NPAPER * 4];
__device__ float g_elb[NPAPER * 4];
__device__ float g_erb[NAUTH  * 4];
__device__ float g_jp [NPAPER * 4];
__device__ float g_ja [NAUTH  * 4];
// CSR scratch
__device__ int g_cnt [NPAPER];
__device__ int g_offc[NPAPER + 1];
__device__ int g_offw[NPAPER + 1];
__device__ int g_offb[NAUTH + 1];
__device__ int g_eidc[NEC];
__device__ int g_eidw[NEW_];
__device__ int g_eidb[NEB];

// ---------------- helpers ----------------
__device__ __forceinline__ float rna_tf32(float f) {
    unsigned u;
    asm("cvt.rna.tf32.f32 %0, %1;" : "=r"(u) : "f"(f));
    return __uint_as_float(u);
}

__global__ void k_izero(int* __restrict__ p, int n) {
    int i = blockIdx.x * blockDim.x + threadIdx.x;
    int stride = gridDim.x * blockDim.x;
    for (; i < n; i += stride) p[i] = 0;
}

__global__ void k_cvt_tf32(const float* __restrict__ in, float* __restrict__ out, int n4) {
    int i = blockIdx.x * blockDim.x + threadIdx.x;
    int stride = gridDim.x * blockDim.x;
    for (; i < n4; i += stride) {
        float4 v = ((const float4*)in)[i];
        v.x = rna_tf32(v.x); v.y = rna_tf32(v.y);
        v.z = rna_tf32(v.z); v.w = rna_tf32(v.w);
        ((float4*)out)[i] = v;
    }
}

// pack weights W[(3,K,512)] relations [r0, r0+nrel) -> out[k][(q*512)+n], tf32
__global__ void k_pack_w(const float* __restrict__ W, float* __restrict__ out,
                         int K, int r0, int nrel) {
    int total = K * nrel * 128;
    int i = blockIdx.x * blockDim.x + threadIdx.x;
    int stride = gridDim.x * blockDim.x;
    for (; i < total; i += stride) {
        int n4 = i & 127;
        int kq = i >> 7;
        int q = kq % nrel, k = kq / nrel;
        float4 v = ((const float4*)(W + ((size_t)(r0 + q) * K + k) * 512))[n4];
        v.x = rna_tf32(v.x); v.y = rna_tf32(v.y);
        v.z = rna_tf32(v.z); v.w = rna_tf32(v.w);
        ((float4*)(out + ((size_t)k * nrel + q) * 512))[n4] = v;
    }
}

__global__ void k_pack_lin(const float* __restrict__ linW, float* __restrict__ out) {
    int i = blockIdx.x * blockDim.x + threadIdx.x;
    if (i >= 512 * 256) return;
    int k = i >> 8, c = i & 255;
    out[i] = (c < NCLS) ? rna_tf32(linW[k * NCLS + c]) : 0.0f;
}

__global__ void k_bias_out(const float* __restrict__ CO, const float* __restrict__ bias,
                           float* __restrict__ out, int M) {
    int i = blockIdx.x * blockDim.x + threadIdx.x;
    int stride = gridDim.x * blockDim.x;
    int total = M * NCLS;
    for (; i < total; i += stride) {
        int r = i / NCLS, c = i - r * NCLS;
        out[i] = CO[(size_t)r * 256 + c] + bias[c];
    }
}

// ---------------- CSR build ----------------
__global__ void k_hist(const int* __restrict__ dst, int E, int* __restrict__ cnt) {
    int e = blockIdx.x * blockDim.x + threadIdx.x;
    if (e < E) atomicAdd(&cnt[dst[e]], 1);
}

__global__ void k_scan(const int* __restrict__ cnt, int* __restrict__ off, int n) {
    __shared__ int sh[1024];
    int tid = threadIdx.x;
    int C = (n + 1023) / 1024;
    int b = tid * C;
    int sum = 0;
    for (int i = 0; i < C; i++)
        if (b + i < n) sum += cnt[b + i];
    sh[tid] = sum;
    __syncthreads();
    for (int d = 1; d < 1024; d <<= 1) {
        int t = 0;
        if (tid >= d) t = sh[tid - d];
        __syncthreads();
        if (tid >= d) sh[tid] += t;
        __syncthreads();
    }
    int run = sh[tid] - sum;
    for (int i = 0; i < C; i++) {
        if (b + i < n) { off[b + i] = run; run += cnt[b + i]; }
    }
    if (tid == 1023) off[n] = sh[1023];
}

__global__ void k_scatter(const int* __restrict__ dst, int E,
                          const int* __restrict__ off, int* __restrict__ cur,
                          int* __restrict__ eid) {
    int e = blockIdx.x * blockDim.x + threadIdx.x;
    if (e >= E) return;
    int d = dst[e];
    int p = off[d] + atomicAdd(&cur[d], 1);
    eid[p] = e;
}

// ---------------- TF32 tensor-core GEMM, 3-stage cp.async pipeline ----------------
#define AS_STRIDE 20
#define BS_STRIDE 136
#define GSTAGES 3
#define SMEM_GEMM ((GSTAGES * 128 * AS_STRIDE + GSTAGES * 16 * BS_STRIDE) * 4)

__device__ __forceinline__ uint32_t smem_u32(const void* p) {
    uint32_t a;
    asm("{ .reg .u64 t; cvta.to.shared.u64 t, %1; cvt.u32.u64 %0, t; }" : "=r"(a) : "l"(p));
    return a;
}

__device__ __forceinline__ void cp16(uint32_t s, const float* g, bool v) {
    asm volatile("cp.async.cg.shared.global [%0], [%1], 16, %2;"
                 :: "r"(s), "l"(__cvta_generic_to_global(g)), "r"(v ? 16 : 0));
}

__device__ __forceinline__ void gemm_issue_tile(
    float* Asb, float* Bsb, int s,
    const float* __restrict__ A, const float* __restrict__ B,
    int bm, int bn, int M, int N, int K, int k0, int tid)
{
    int am = tid >> 2, ac4 = tid & 3;
    int bk = tid >> 5, bc4 = tid & 31;
    float* As = Asb + s * 128 * AS_STRIDE;
    float* Bs = Bsb + s * 16 * BS_STRIDE;
#pragma unroll
    for (int i = 0; i < 2; i++) {
        int m = am + i * 64;
        int mm = bm + m;
        int msafe = mm < M ? mm : (M - 1);
        cp16(smem_u32(As + m * AS_STRIDE + ac4 * 4),
             A + (size_t)msafe * K + k0 + ac4 * 4, mm < M);
    }
#pragma unroll
    for (int i = 0; i < 2; i++) {
        int kr = bk + i * 8;
        cp16(smem_u32(Bs + kr * BS_STRIDE + bc4 * 4),
             B + (size_t)(k0 + kr) * N + bn + bc4 * 4, true);
    }
    asm volatile("cp.async.commit_group;" ::: "memory");
}

__global__ __launch_bounds__(256) void k_tf32_gemm(
    const float* __restrict__ A, const float* __restrict__ B,
    float* __restrict__ C, int M, int N, int K)
{
    extern __shared__ float sm[];
    float* Asb = sm;
    float* Bsb = sm + GSTAGES * 128 * AS_STRIDE;

    int tid = threadIdx.x;
    int lane = tid & 31;
    int wid = tid >> 5;
    int warp_m = wid & 3;
    int warp_n = wid >> 2;
    int gr = lane >> 2;
    int gc = lane & 3;

    int bm = blockIdx.y * 128;
    int bn = blockIdx.x * 128;

    float acc[2][8][4];
#pragma unroll
    for (int mi = 0; mi < 2; mi++)
#pragma unroll
        for (int ni = 0; ni < 8; ni++)
#pragma unroll
            for (int j = 0; j < 4; j++) acc[mi][ni][j] = 0.0f;

    int nt = K >> 4;

    // prologue: issue first 2 tiles
    gemm_issue_tile(Asb, Bsb, 0, A, B, bm, bn, M, N, K, 0, tid);
    if (nt > 1)
        gemm_issue_tile(Asb, Bsb, 1, A, B, bm, bn, M, N, K, 16, tid);

#pragma unroll 1
    for (int t = 0; t < nt; t++) {
        if (t + 1 < nt)
            asm volatile("cp.async.wait_group 1;" ::: "memory");
        else
            asm volatile("cp.async.wait_group 0;" ::: "memory");
        __syncthreads();

        if (t + 2 < nt)
            gemm_issue_tile(Asb, Bsb, (t + 2) % GSTAGES, A, B, bm, bn, M, N, K,
                            (t + 2) * 16, tid);

        float* As = Asb + (t % GSTAGES) * 128 * AS_STRIDE;
        float* Bs = Bsb + (t % GSTAGES) * 16 * BS_STRIDE;
#pragma unroll
        for (int ks = 0; ks < 2; ks++) {
            int k0 = ks * 8;
            unsigned af[2][4];
#pragma unroll
            for (int mi = 0; mi < 2; mi++) {
                int m0 = warp_m * 32 + mi * 16 + gr;
                af[mi][0] = __float_as_uint(As[m0 * AS_STRIDE + k0 + gc]);
                af[mi][1] = __float_as_uint(As[(m0 + 8) * AS_STRIDE + k0 + gc]);
                af[mi][2] = __float_as_uint(As[m0 * AS_STRIDE + k0 + gc + 4]);
                af[mi][3] = __float_as_uint(As[(m0 + 8) * AS_STRIDE + k0 + gc + 4]);
            }
            unsigned bf[8][2];
#pragma unroll
            for (int ni = 0; ni < 8; ni++) {
                int n0 = warp_n * 64 + ni * 8 + gr;
                bf[ni][0] = __float_as_uint(Bs[(k0 + gc) * BS_STRIDE + n0]);
                bf[ni][1] = __float_as_uint(Bs[(k0 + gc + 4) * BS_STRIDE + n0]);
            }
#pragma unroll
            for (int mi = 0; mi < 2; mi++)
#pragma unroll
                for (int ni = 0; ni < 8; ni++) {
                    asm volatile(
                        "mma.sync.aligned.m16n8k8.row.col.f32.tf32.tf32.f32 "
                        "{%0,%1,%2,%3}, {%4,%5,%6,%7}, {%8,%9}, {%0,%1,%2,%3};"
                        : "+f"(acc[mi][ni][0]), "+f"(acc[mi][ni][1]),
                          "+f"(acc[mi][ni][2]), "+f"(acc[mi][ni][3])
                        : "r"(af[mi][0]), "r"(af[mi][1]), "r"(af[mi][2]), "r"(af[mi][3]),
                          "r"(bf[ni][0]), "r"(bf[ni][1]));
                }
        }
        __syncthreads();
    }

#pragma unroll
    for (int mi = 0; mi < 2; mi++) {
#pragma unroll
        for (int ni = 0; ni < 8; ni++) {
            int r0 = bm + warp_m * 32 + mi * 16 + gr;
            int cn = bn + warp_n * 64 + ni * 8 + gc * 2;
            if (r0 < M) {
                float2 v = make_float2(acc[mi][ni][0], acc[mi][ni][1]);
                *(float2*)(C + (size_t)r0 * N + cn) = v;
            }
            if (r0 + 8 < M) {
                float2 v = make_float2(acc[mi][ni][2], acc[mi][ni][3]);
                *(float2*)(C + (size_t)(r0 + 8) * N + cn) = v;
            }
        }
    }
}

// ---------------- multi-relation attention dots ----------------
// warp per node; computes el/er for nrel relations packed in Z (512 cols each).
__global__ void k_dots3(const float* __restrict__ Z, int zs4,
                        const float* __restrict__ al, const float* __restrict__ ar,
                        int nrel,
                        float* __restrict__ el0, float* __restrict__ er0,
                        float* __restrict__ el1, float* __restrict__ er1,
                        float* __restrict__ el2, float* __restrict__ er2,
                        int Nn)
{
    int w = (blockIdx.x * blockDim.x + threadIdx.x) >> 5;
    int lane = threadIdx.x & 31;
    if (w >= Nn) return;
    const float4* zp = (const float4*)Z + (size_t)w * zs4;
    const float4* alp = (const float4*)al;
    const float4* arp = (const float4*)ar;

    for (int r = 0; r < nrel; r++) {
        float sl[4], sr[4];
#pragma unroll
        for (int i = 0; i < 4; i++) {
            float4 z = zp[r * 128 + i * 32 + lane];
            float4 a = alp[r * 128 + i * 32 + lane];
            float4 b = arp[r * 128 + i * 32 + lane];
            sl[i] = z.x * a.x + z.y * a.y + z.z * a.z + z.w * a.w;
            sr[i] = z.x * b.x + z.y * b.y + z.z * b.z + z.w * b.w;
        }
#pragma unroll
        for (int o = 16; o > 0; o >>= 1) {
#pragma unroll
            for (int i = 0; i < 4; i++) {
                sl[i] += __shfl_down_sync(0xffffffffu, sl[i], o);
                sr[i] += __shfl_down_sync(0xffffffffu, sr[i], o);
            }
        }
        if (lane == 0) {
            float* el = (r == 0) ? el0 : (r == 1) ? el1 : el2;
            float* er = (r == 0) ? er0 : (r == 1) ? er1 : er2;
#pragma unroll
            for (int i = 0; i < 4; i++) {
                el[w * 4 + i] = sl[i];
                er[w * 4 + i] = sr[i];
            }
        }
    }
}

// ---------------- fused GAT aggregation ----------------
__device__ __forceinline__ float leaky02(float v) { return v > 0.f ? v : 0.2f * v; }

__device__ __forceinline__ void gat_side(
    const int* __restrict__ off, const int* __restrict__ eid,
    const int* __restrict__ src,
    const float* __restrict__ el, float4 r4,
    const float* __restrict__ Z, int zs4,
    int w, int lane, float4 accv[4])
{
    int beg = off[w], end = off[w + 1];
    if (beg >= end) return;

    float m[4] = {-1e30f, -1e30f, -1e30f, -1e30f};
    for (int i = beg + lane; i < end; i += 32) {
        int sn = src[eid[i]];
        float4 e4 = ((const float4*)el)[sn];
        m[0] = fmaxf(m[0], leaky02(e4.x + r4.x));
        m[1] = fmaxf(m[1], leaky02(e4.y + r4.y));
        m[2] = fmaxf(m[2], leaky02(e4.z + r4.z));
        m[3] = fmaxf(m[3], leaky02(e4.w + r4.w));
    }
#pragma unroll
    for (int o = 16; o > 0; o >>= 1) {
#pragma unroll
        for (int k = 0; k < 4; k++)
            m[k] = fmaxf(m[k], __shfl_xor_sync(0xffffffffu, m[k], o));
    }

    float s[4] = {0.f, 0.f, 0.f, 0.f};
    for (int i = beg + lane; i < end; i += 32) {
        int sn = src[eid[i]];
        float4 e4 = ((const float4*)el)[sn];
        s[0] += expf(leaky02(e4.x + r4.x) - m[0]);
        s[1] += expf(leaky02(e4.y + r4.y) - m[1]);
        s[2] += expf(leaky02(e4.z + r4.z) - m[2]);
        s[3] += expf(leaky02(e4.w + r4.w) - m[3]);
    }
#pragma unroll
    for (int o = 16; o > 0; o >>= 1) {
#pragma unroll
        for (int k = 0; k < 4; k++)
            s[k] += __shfl_xor_sync(0xffffffffu, s[k], o);
    }
    float inv[4];
#pragma unroll
    for (int k = 0; k < 4; k++) inv[k] = 1.0f / (s[k] + 1e-9f);

    for (int i = beg; i < end; i++) {
        int sn = src[eid[i]];
        float4 e4 = ((const float4*)el)[sn];
        float a0 = expf(leaky02(e4.x + r4.x) - m[0]) * inv[0];
        float a1 = expf(leaky02(e4.y + r4.y) - m[1]) * inv[1];
        float a2 = expf(leaky02(e4.z + r4.z) - m[2]) * inv[2];
        float a3 = expf(leaky02(e4.w + r4.w) - m[3]) * inv[3];
        const float4* zp = (const float4*)Z + (size_t)sn * zs4;
        float4 z0 = zp[0 * 32 + lane];
        float4 z1 = zp[1 * 32 + lane];
        float4 z2 = zp[2 * 32 + lane];
        float4 z3 = zp[3 * 32 + lane];
        accv[0].x += a0 * z0.x; accv[0].y += a0 * z0.y;
        accv[0].z += a0 * z0.z; accv[0].w += a0 * z0.w;
        accv[1].x += a1 * z1.x; accv[1].y += a1 * z1.y;
        accv[1].z += a1 * z1.z; accv[1].w += a1 * z1.w;
        accv[2].x += a2 * z2.x; accv[2].y += a2 * z2.y;
        accv[2].z += a2 * z2.z; accv[2].w += a2 * z2.w;
        accv[3].x += a3 * z3.x; accv[3].y += a3 * z3.y;
        accv[3].z += a3 * z3.z; accv[3].w += a3 * z3.w;
    }
}

// merged paper GAT: cites (from ZP) + writes (from ZA) into OP, relu+round, one store
__global__ void k_gat_paper(
    const int* __restrict__ offc, const int* __restrict__ eidc, const int* __restrict__ csrc,
    const float* __restrict__ elc, const float* __restrict__ erc,
    const float* __restrict__ ZP, int zp4,
    const int* __restrict__ offw, const int* __restrict__ eidw, const int* __restrict__ wsrc,
    const float* __restrict__ elw, const float* __restrict__ erw,
    const float* __restrict__ ZA, int za4,
    float* __restrict__ out, int nDst, int dorelu)
{
    int w = (blockIdx.x * blockDim.x + threadIdx.x) >> 5;
    if (w >= nDst) return;
    int lane = threadIdx.x & 31;

    float4 accv[4];
#pragma unroll
    for (int j = 0; j < 4; j++) accv[j] = make_float4(0.f, 0.f, 0.f, 0.f);

    gat_side(offc, eidc, csrc, elc, ((const float4*)erc)[w], ZP, zp4, w, lane, accv);
    gat_side(offw, eidw, wsrc, elw, ((const float4*)erw)[w], ZA, za4, w, lane, accv);

#pragma unroll
    for (int j = 0; j < 4; j++) {
        if (dorelu) {
            accv[j].x = fmaxf(accv[j].x, 0.f);
            accv[j].y = fmaxf(accv[j].y, 0.f);
            accv[j].z = fmaxf(accv[j].z, 0.f);
            accv[j].w = fmaxf(accv[j].w, 0.f);
        }
        accv[j].x = rna_tf32(accv[j].x);
        accv[j].y = rna_tf32(accv[j].y);
        accv[j].z = rna_tf32(accv[j].z);
        accv[j].w = rna_tf32(accv[j].w);
    }
    float4* op = (float4*)out + (size_t)w * 128;
#pragma unroll
    for (int j = 0; j < 4; j++) op[j * 32 + lane] = accv[j];
}

// single-relation GAT (authors, wb)
__global__ void k_gat_single(
    const int* __restrict__ off, const int* __restrict__ eid, const int* __restrict__ src,
    const float* __restrict__ el, const float* __restrict__ er,
    const float* __restrict__ Z, int zs4,
    float* __restrict__ out, int nDst, int dorelu)
{
    int w = (blockIdx.x * blockDim.x + threadIdx.x) >> 5;
    if (w >= nDst) return;
    int lane = threadIdx.x & 31;

    float4 accv[4];
#pragma unroll
    for (int j = 0; j < 4; j++) accv[j] = make_float4(0.f, 0.f, 0.f, 0.f);

    gat_side(off, eid, src, el, ((const float4*)er)[w], Z, zs4, w, lane, accv);

#pragma unroll
    for (int j = 0; j < 4; j++) {
        if (dorelu) {
            accv[j].x = fmaxf(accv[j].x, 0.f);
            accv[j].y = fmaxf(accv[j].y, 0.f);
            accv[j].z = fmaxf(accv[j].z, 0.f);
            accv[j].w = fmaxf(accv[j].w, 0.f);
        }
        accv[j].x = rna_tf32(accv[j].x);
        accv[j].y = rna_tf32(accv[j].y);
        accv[j].z = rna_tf32(accv[j].z);
        accv[j].w = rna_tf32(accv[j].w);
    }
    float4* op = (float4*)out + (size_t)w * 128;
#pragma unroll
    for (int j = 0; j < 4; j++) op[j * 32 + lane] = accv[j];
}

// ---------------- host-side launch helpers ----------------
static inline void launch_gemm_tf32(const float* A, const float* B, float* C,
                                    int M, int N, int K)
{
    dim3 grid(N / 128, (M + 127) / 128);
    k_tf32_gemm<<<grid, 256, SMEM_GEMM>>>(A, B, C, M, N, K);
}

static inline void launch_cvt(const float* in, float* out, size_t n)
{
    int n4 = (int)(n / 4);
    int blocks = (n4 + 255) / 256;
    if (blocks > 2048) blocks = 2048;
    k_cvt_tf32<<<blocks, 256>>>(in, out, n4);
}

static inline void build_csr(const int* dst, int E, int nDst,
                             int* cnt, int* off, int* eid)
{
    k_izero<<<(nDst + 255) / 256, 256>>>(cnt, nDst);
    k_hist<<<(E + 255) / 256, 256>>>(dst, E, cnt);
    k_scan<<<1, 1024>>>(cnt, off, nDst);
    k_izero<<<(nDst + 255) / 256, 256>>>(cnt, nDst);
    k_scatter<<<(E + 255) / 256, 256>>>(dst, E, off, cnt, eid);
}

static inline void launch_pack_w(const float* W, float* out, int K, int r0, int nrel)
{
    int total = K * nrel * 128;
    int blocks = (total + 255) / 256;
    if (blocks > 2048) blocks = 2048;
    k_pack_w<<<blocks, 256>>>(W, out, K, r0, nrel);
}

extern "C" void kernel_launch(void* const* d_in, const int* in_sizes, int n_in,
                              void* d_out, int out_size)
{
    const float* x_paper  = (const float*)d_in[0];
    const float* x_author = (const float*)d_in[1];
    const int* cs = (const int*)d_in[2];
    const int* cd = (const int*)d_in[3];
    const int* ws = (const int*)d_in[4];
    const int* wd = (const int*)d_in[5];
    const int* bsrc = (const int*)d_in[6];
    const int* bdst = (const int*)d_in[7];
    const float* Wt[3] = { (const float*)d_in[8],  (const float*)d_in[11], (const float*)d_in[14] };
    const float* AL[3] = { (const float*)d_in[9],  (const float*)d_in[12], (const float*)d_in[15] };
    const float* AR[3] = { (const float*)d_in[10], (const float*)d_in[13], (const float*)d_in[16] };
    const float* linW = (const float*)d_in[17];
    const float* linb = (const float*)d_in[18];
    float* out = (float*)d_out;

    cudaFuncSetAttribute(k_tf32_gemm, cudaFuncAttributeMaxDynamicSharedMemorySize, SMEM_GEMM);

    float *ZP, *ZA, *OP, *OA, *Ap, *Aa, *Wp, *Wa, *lin;
    float *elc, *erc, *elw, *erw, *elb, *erb, *jp, *ja;
    int *cnt, *offc, *offw, *offb, *eidc, *eidw, *eidb;
    cudaGetSymbolAddress((void**)&ZP,  g_ZP);
    cudaGetSymbolAddress((void**)&ZA,  g_ZA);
    cudaGetSymbolAddress((void**)&OP,  g_OP);
    cudaGetSymbolAddress((void**)&OA,  g_OA);
    cudaGetSymbolAddress((void**)&Ap,  g_Ap);
    cudaGetSymbolAddress((void**)&Aa,  g_Aa);
    cudaGetSymbolAddress((void**)&Wp,  g_Wp);
    cudaGetSymbolAddress((void**)&Wa,  g_Wa);
    cudaGetSymbolAddress((void**)&lin, g_lin);
    cudaGetSymbolAddress((void**)&elc, g_elc);
    cudaGetSymbolAddress((void**)&erc, g_erc);
    cudaGetSymbolAddress((void**)&elw, g_elw);
    cudaGetSymbolAddress((void**)&erw, g_erw);
    cudaGetSymbolAddress((void**)&elb, g_elb);
    cudaGetSymbolAddress((void**)&erb, g_erb);
    cudaGetSymbolAddress((void**)&jp,  g_jp);
    cudaGetSymbolAddress((void**)&ja,  g_ja);
    cudaGetSymbolAddress((void**)&cnt,  g_cnt);
    cudaGetSymbolAddress((void**)&offc, g_offc);
    cudaGetSymbolAddress((void**)&offw, g_offw);
    cudaGetSymbolAddress((void**)&offb, g_offb);
    cudaGetSymbolAddress((void**)&eidc, g_eidc);
    cudaGetSymbolAddress((void**)&eidw, g_eidw);
    cudaGetSymbolAddress((void**)&eidb, g_eidb);

    // CSR for the three edge types (reused across layers)
    build_csr(cd,   NEC,  NPAPER, cnt, offc, eidc);
    build_csr(wd,   NEW_, NPAPER, cnt, offw, eidw);
    build_csr(bdst, NEB,  NAUTH,  cnt, offb, eidb);

    // layer-0 activation conversion (later layers written tf32-rounded by GAT)
    launch_cvt(x_paper,  Ap, (size_t)NPAPER * 1024);
    launch_cvt(x_author, Aa, (size_t)NAUTH * 1024);

    for (int L = 0; L < 3; ++L) {
        const float* hp = (L == 0) ? Ap : OP;
        const float* ha = (L == 0) ? Aa : OA;
        int K = (L == 0) ? 1024 : 512;
        const float* al = AL[L];
        const float* ar = AR[L];
        int relu = (L < 2) ? 1 : 0;
        int last = (L == 2);

        int nrp = last ? 2 : 3;
        int nra = last ? 1 : 2;
        int Np = nrp * 512, Na = nra * 512;
        launch_pack_w(Wt[L], Wp, K, 0, nrp);
        launch_pack_w(Wt[L], Wa, K, 1, nra);

        launch_gemm_tf32(hp, Wp, ZP, NPAPER, Np, K);
        launch_gemm_tf32(ha, Wa, ZA, NAUTH, Na, K);

        int zp4 = Np / 4, za4 = Na / 4;

        // attention logits: papers (rel0=cites el/er, rel1=writes dst er, rel2=wb src el)
        {
            int thr = NPAPER * 32;
            k_dots3<<<(thr + 255) / 256, 256>>>(ZP, zp4, al, ar, nrp,
                                                elc, erc, jp, erw, elb, jp, NPAPER);
        }
        // authors (rel1=writes src el, rel2=wb dst er)
        {
            int thr = NAUTH * 32;
            k_dots3<<<(thr + 255) / 256, 256>>>(ZA, za4, al + 512, ar + 512, nra,
                                                elw, ja, ja, erb, ja, ja, NAUTH);
        }

        // merged paper aggregation (cites + writes), fused relu + tf32 round
        {
            int thr = NPAPER * 32;
            k_gat_paper<<<(thr + 255) / 256, 256>>>(
                offc, eidc, cs, elc, erc, ZP, zp4,
                offw, eidw, ws, elw, erw, ZA, za4,
                OP, NPAPER, relu);
        }
        // author aggregation (wb) — not needed in last layer
        if (!last) {
            int thr = NAUTH * 32;
            k_gat_single<<<(thr + 255) / 256, 256>>>(
                offb, eidb, bsrc, elb, erb, ZP + 1024, zp4, OA, NAUTH, relu);
        }
    }

    // classifier: tf32 GEMM into padded scratch, then bias + copy-out
    k_pack_lin<<<(512 * 256 + 255) / 256, 256>>>(linW, lin);
    launch_gemm_tf32(OP, lin, Ap, NPAPER, 256, HIDDEN);
    {
        int total = NPAPER * NCLS;
        int blocks = (total + 255) / 256;
        if (blocks > 4096) blocks = 4096;
        k_bias_out<<<blocks, 256>>>(Ap, linb, out, NPAPER);
    }
}